// round 1
// baseline (speedup 1.0000x reference)
#include <cuda_runtime.h>
#include <cstdint>
#include <cstddef>

#define USERS 50000
#define ITEMS 50000
#define NTOT  100000
#define DIM   128

// ---------------- scratch (device globals; allocation-free) ----------------
__device__ float g_allID [(size_t)ITEMS * DIM];
__device__ float g_allFeat[(size_t)ITEMS * DIM];
__device__ float g_Id    [(size_t)NTOT * DIM];
__device__ float g_Id2   [(size_t)NTOT * DIM];
__device__ float g_IdAdj [(size_t)NTOT * DIM];
__device__ float g_Ft    [(size_t)NTOT * DIM];
__device__ float g_Ft2   [(size_t)NTOT * DIM];
__device__ float g_FtAdj [(size_t)NTOT * DIM];
__device__ float g_modal [(size_t)NTOT * DIM];
__device__ float g_tmpA  [(size_t)NTOT * DIM];
__device__ float g_tmpB  [(size_t)NTOT * DIM];

// ---------------- zero ----------------
__global__ void zero_kernel(float4* __restrict__ p, int n4) {
    int i = blockIdx.x * blockDim.x + threadIdx.x;
    if (i < n4) p[i] = make_float4(0.f, 0.f, 0.f, 0.f);
}

// ---------------- GEMM: C = (acc? C:0) + w * leaky_relu(A @ B) ----------------
// A: M x K row-major, B: K x 128 row-major, C: M x 128. BM=64, BN=128, BK=16, 256 thr.
__global__ __launch_bounds__(256) void gemm_lrelu_kernel(
    const float* __restrict__ A, const float* __restrict__ B,
    float* __restrict__ C, int M, int K,
    const float* __restrict__ mw, int widx, int accumulate)
{
    __shared__ float As[16][64];    // [k][m]
    __shared__ float Bs[16][128];   // [k][n]

    int tid = threadIdx.x;
    int tx = tid & 15;          // 0..15 -> 8 cols each
    int ty = tid >> 4;          // 0..15 -> 4 rows each
    int blockRow = blockIdx.x * 64;

    float acc[4][8];
#pragma unroll
    for (int i = 0; i < 4; i++)
#pragma unroll
        for (int j = 0; j < 8; j++) acc[i][j] = 0.f;

    int arow = tid >> 2;            // 0..63
    int acol = (tid & 3) << 2;      // 0,4,8,12
    int brow = tid >> 5;            // 0..7
    int bcol = (tid & 31) << 2;     // 0..124

    for (int k0 = 0; k0 < K; k0 += 16) {
        int gm = blockRow + arow;
        float4 av = make_float4(0.f, 0.f, 0.f, 0.f);
        if (gm < M) av = *(const float4*)(A + (size_t)gm * K + k0 + acol);
        As[acol + 0][arow] = av.x;
        As[acol + 1][arow] = av.y;
        As[acol + 2][arow] = av.z;
        As[acol + 3][arow] = av.w;
#pragma unroll
        for (int r = 0; r < 2; r++) {
            float4 bv = *(const float4*)(B + (size_t)(k0 + brow + r * 8) * 128 + bcol);
            *(float4*)&Bs[brow + r * 8][bcol] = bv;
        }
        __syncthreads();
#pragma unroll
        for (int kk = 0; kk < 16; kk++) {
            float4 a4 = *(float4*)&As[kk][ty * 4];
            float4 b0 = *(float4*)&Bs[kk][tx * 8];
            float4 b1 = *(float4*)&Bs[kk][tx * 8 + 4];
            float a[4] = {a4.x, a4.y, a4.z, a4.w};
            float b[8] = {b0.x, b0.y, b0.z, b0.w, b1.x, b1.y, b1.z, b1.w};
#pragma unroll
            for (int i = 0; i < 4; i++)
#pragma unroll
                for (int j = 0; j < 8; j++)
                    acc[i][j] = fmaf(a[i], b[j], acc[i][j]);
        }
        __syncthreads();
    }

    // softmax(modal_weight)[widx]
    float m0 = mw[0], m1 = mw[1];
    float mx = fmaxf(m0, m1);
    float e0 = __expf(m0 - mx), e1 = __expf(m1 - mx);
    float w = ((widx == 0) ? e0 : e1) / (e0 + e1);

#pragma unroll
    for (int i = 0; i < 4; i++) {
        int gm = blockRow + ty * 4 + i;
        if (gm >= M) continue;
        float* crow = C + (size_t)gm * 128 + tx * 8;
#pragma unroll
        for (int j = 0; j < 8; j++) {
            float v = acc[i][j];
            v = (v > 0.f) ? v : 0.2f * v;   // leaky_relu(0.2)
            v *= w;
            crow[j] = accumulate ? (crow[j] + v) : v;
        }
    }
}

// ---------------- row-wise L2 normalize in place (warp per row, DIM=128) ----------------
__global__ void l2norm_rows_kernel(float* __restrict__ x, int nrows)
{
    int wid = (blockIdx.x * blockDim.x + threadIdx.x) >> 5;
    int lane = threadIdx.x & 31;
    if (wid >= nrows) return;
    float4* p = (float4*)(x + (size_t)wid * DIM) + lane;
    float4 v = *p;
    float s = v.x * v.x + v.y * v.y + v.z * v.z + v.w * v.w;
#pragma unroll
    for (int o = 16; o > 0; o >>= 1) s += __shfl_xor_sync(0xffffffffu, s, o);
    float inv = 1.f / fmaxf(sqrtf(s), 1e-12f);
    v.x *= inv; v.y *= inv; v.z *= inv; v.w *= inv;
    *p = v;
}

// ---------------- SpMM: out[row] += val * x[col]  (warp per edge, D=128) ----------------
// x[col] = col < USERS ? xU[col] : xI[col-USERS]
__global__ void spmm_kernel(const int* __restrict__ rows, const int* __restrict__ cols,
                            const float* __restrict__ vals,
                            const float* __restrict__ xU, const float* __restrict__ xI,
                            float* __restrict__ out, int nnz)
{
    int e = (blockIdx.x * blockDim.x + threadIdx.x) >> 5;
    int lane = threadIdx.x & 31;
    if (e >= nnz) return;
    int r = rows[e];
    int c = cols[e];
    float v = vals[e];
    const float* x = (c < USERS) ? (xU + (size_t)c * DIM) : (xI + (size_t)(c - USERS) * DIM);
    float4 xv = *(const float4*)(x + lane * 4);
    float* o = out + (size_t)r * DIM + lane * 4;
    asm volatile("red.global.add.v4.f32 [%0], {%1, %2, %3, %4};"
                 :: "l"(o), "f"(xv.x * v), "f"(xv.y * v), "f"(xv.z * v), "f"(xv.w * v)
                 : "memory");
}

// ---------------- combine: modal = 0.5*(Id+Id2+0.2*IdAdj) + 0.5*(Ft+Ft2+0.2*FtAdj) ----------------
__global__ void combine_kernel(const float4* __restrict__ id, const float4* __restrict__ id2,
                               const float4* __restrict__ idadj,
                               const float4* __restrict__ ft, const float4* __restrict__ ft2,
                               const float4* __restrict__ ftadj,
                               float4* __restrict__ modal, int n4)
{
    int i = blockIdx.x * blockDim.x + threadIdx.x;
    if (i >= n4) return;
    float4 a = id[i], b = id2[i], c = idadj[i];
    float4 d = ft[i], e = ft2[i], f = ftadj[i];
    float4 m;
    m.x = 0.5f * (a.x + b.x + 0.2f * c.x) + 0.5f * (d.x + e.x + 0.2f * f.x);
    m.y = 0.5f * (a.y + b.y + 0.2f * c.y) + 0.5f * (d.y + e.y + 0.2f * f.y);
    m.z = 0.5f * (a.z + b.z + 0.2f * c.z) + 0.5f * (d.z + e.z + 0.2f * f.z);
    m.w = 0.5f * (a.w + b.w + 0.2f * c.w) + 0.5f * (d.w + e.w + 0.2f * f.w);
    modal[i] = m;
}

// ---------------- final: out = modal + A + B + 0.5 * l2norm(modal)  (warp per row) ----------------
__global__ void final_kernel(const float* __restrict__ modal, const float* __restrict__ A,
                             const float* __restrict__ B, float* __restrict__ out, int nrows)
{
    int wid = (blockIdx.x * blockDim.x + threadIdx.x) >> 5;
    int lane = threadIdx.x & 31;
    if (wid >= nrows) return;
    size_t off = (size_t)wid * DIM + lane * 4;
    float4 m = *(const float4*)(modal + off);
    float4 a = *(const float4*)(A + off);
    float4 b = *(const float4*)(B + off);
    float s = m.x * m.x + m.y * m.y + m.z * m.z + m.w * m.w;
#pragma unroll
    for (int o = 16; o > 0; o >>= 1) s += __shfl_xor_sync(0xffffffffu, s, o);
    float inv = 0.5f / fmaxf(sqrtf(s), 1e-12f);   // RIS_LAMBDA * (1/norm)
    float4 r;
    r.x = m.x + a.x + b.x + inv * m.x;
    r.y = m.y + a.y + b.y + inv * m.y;
    r.z = m.z + a.z + b.z + inv * m.z;
    r.w = m.w + a.w + b.w + inv * m.w;
    *(float4*)(out + off) = r;
}

// ---------------- host ----------------
static inline void zero_buf(float* p, size_t nfloats) {
    int n4 = (int)(nfloats / 4);
    zero_kernel<<<(n4 + 255) / 256, 256>>>((float4*)p, n4);
}

extern "C" void kernel_launch(void* const* d_in, const int* in_sizes, int n_in,
                              void* d_out, int out_size)
{
    const int*   adj_rows = (const int*)d_in[0];
    const int*   adj_cols = (const int*)d_in[1];
    const float* adj_vals = (const float*)d_in[2];
    const int*   id_rows  = (const int*)d_in[3];
    const int*   id_cols  = (const int*)d_in[4];
    const float* id_vals  = (const float*)d_in[5];
    const int*   ft_rows  = (const int*)d_in[6];
    const int*   ft_cols  = (const int*)d_in[7];
    const float* ft_vals  = (const float*)d_in[8];
    const float* uEmb     = (const float*)d_in[9];
    const float* iEmb     = (const float*)d_in[10];
    const float* img_emb  = (const float*)d_in[11];
    const float* img_id   = (const float*)d_in[12];
    const float* txt_emb  = (const float*)d_in[13];
    const float* txt_id   = (const float*)d_in[14];
    const float* img_tr   = (const float*)d_in[15];
    const float* img_id_tr= (const float*)d_in[16];
    const float* txt_tr   = (const float*)d_in[17];
    const float* txt_id_tr= (const float*)d_in[18];
    const float* mw       = (const float*)d_in[19];
    float* out = (float*)d_out;

    int E_adj = in_sizes[0];
    int E_id  = in_sizes[3];
    int E_ft  = in_sizes[6];

    float *pAllID, *pAllFeat, *pId, *pId2, *pIdAdj, *pFt, *pFt2, *pFtAdj, *pModal, *pA, *pB;
    cudaGetSymbolAddress((void**)&pAllID,  g_allID);
    cudaGetSymbolAddress((void**)&pAllFeat,g_allFeat);
    cudaGetSymbolAddress((void**)&pId,     g_Id);
    cudaGetSymbolAddress((void**)&pId2,    g_Id2);
    cudaGetSymbolAddress((void**)&pIdAdj,  g_IdAdj);
    cudaGetSymbolAddress((void**)&pFt,     g_Ft);
    cudaGetSymbolAddress((void**)&pFt2,    g_Ft2);
    cudaGetSymbolAddress((void**)&pFtAdj,  g_FtAdj);
    cudaGetSymbolAddress((void**)&pModal,  g_modal);
    cudaGetSymbolAddress((void**)&pA,      g_tmpA);
    cudaGetSymbolAddress((void**)&pB,      g_tmpB);

    const size_t ND = (size_t)NTOT * DIM;

    // 1) zero accumulation buffers
    zero_buf(pId, ND);  zero_buf(pId2, ND);  zero_buf(pIdAdj, ND);
    zero_buf(pFt, ND);  zero_buf(pFt2, ND);  zero_buf(pFtAdj, ND);
    zero_buf(pA, ND);   zero_buf(pB, ND);

    // 2) modality GEMMs: allID = w0*lrelu(img_id@img_id_tr) + w1*lrelu(txt_id@txt_id_tr)
    //                    allFeat = w0*lrelu(img_emb@img_tr) + w1*lrelu(txt_emb@txt_tr)
    int gemm_blocks = (ITEMS + 63) / 64;
    gemm_lrelu_kernel<<<gemm_blocks, 256>>>(img_id,  img_id_tr, pAllID,  ITEMS, 1024, mw, 0, 0);
    gemm_lrelu_kernel<<<gemm_blocks, 256>>>(txt_id,  txt_id_tr, pAllID,  ITEMS,  768, mw, 1, 1);
    gemm_lrelu_kernel<<<gemm_blocks, 256>>>(img_emb, img_tr,    pAllFeat,ITEMS, 1024, mw, 0, 0);
    gemm_lrelu_kernel<<<gemm_blocks, 256>>>(txt_emb, txt_tr,    pAllFeat,ITEMS,  768, mw, 1, 1);

    // 3) row l2-normalize item-side modality embeddings
    int l2_blocks = (ITEMS * 32 + 255) / 256;
    l2norm_rows_kernel<<<l2_blocks, 256>>>(pAllID,   ITEMS);
    l2norm_rows_kernel<<<l2_blocks, 256>>>(pAllFeat, ITEMS);

    // 4) SpMMs
    auto spmm_grid = [](int nnz) { return (nnz * 32 + 255) / 256; };
    spmm_kernel<<<spmm_grid(E_id),  256>>>(id_rows,  id_cols,  id_vals,  uEmb, iEmb,    pIdAdj, E_id);
    spmm_kernel<<<spmm_grid(E_adj), 256>>>(adj_rows, adj_cols, adj_vals, uEmb, pAllID,  pId,    E_adj);
    spmm_kernel<<<spmm_grid(E_adj), 256>>>(adj_rows, adj_cols, adj_vals, pId,  iEmb,    pId2,   E_adj);
    spmm_kernel<<<spmm_grid(E_ft),  256>>>(ft_rows,  ft_cols,  ft_vals,  uEmb, iEmb,    pFtAdj, E_ft);
    spmm_kernel<<<spmm_grid(E_adj), 256>>>(adj_rows, adj_cols, adj_vals, uEmb, pAllFeat,pFt,    E_adj);
    spmm_kernel<<<spmm_grid(E_adj), 256>>>(adj_rows, adj_cols, adj_vals, pFt,  iEmb,    pFt2,   E_adj);

    // 5) combine into modal
    int n4 = (int)(ND / 4);
    combine_kernel<<<(n4 + 255) / 256, 256>>>((float4*)pId, (float4*)pId2, (float4*)pIdAdj,
                                              (float4*)pFt, (float4*)pFt2, (float4*)pFtAdj,
                                              (float4*)pModal, n4);

    // 6) 2-layer GNN propagation (input spans full N: xI = base + USERS*DIM)
    spmm_kernel<<<spmm_grid(E_adj), 256>>>(adj_rows, adj_cols, adj_vals,
                                           pModal, pModal + (size_t)USERS * DIM, pA, E_adj);
    spmm_kernel<<<spmm_grid(E_adj), 256>>>(adj_rows, adj_cols, adj_vals,
                                           pA, pA + (size_t)USERS * DIM, pB, E_adj);

    // 7) final: out = modal + A + B + 0.5 * l2norm(modal)
    int fin_blocks = (NTOT * 32 + 255) / 256;
    final_kernel<<<fin_blocks, 256>>>(pModal, pA, pB, out, NTOT);

    (void)n_in; (void)out_size;
}

// round 2
// speedup vs baseline: 1.7836x; 1.7836x over previous
#include <cuda_runtime.h>
#include <cstdint>
#include <cstddef>

#define USERS 50000
#define ITEMS 50000
#define NTOT  100000
#define DIM   128
#define EMAX  1700000
#define SCAN_BLOCK 1024
#define NB_MAX 128

// ---------------- scratch (device globals; allocation-free) ----------------
__device__ float g_allID [(size_t)ITEMS * DIM];
__device__ float g_allFeat[(size_t)ITEMS * DIM];
__device__ float g_Id    [(size_t)NTOT * DIM];
__device__ float g_Id2   [(size_t)NTOT * DIM];
__device__ float g_IdAdj [(size_t)NTOT * DIM];
__device__ float g_Ft    [(size_t)NTOT * DIM];
__device__ float g_Ft2   [(size_t)NTOT * DIM];
__device__ float g_FtAdj [(size_t)NTOT * DIM];
__device__ float g_modal [(size_t)NTOT * DIM];
__device__ float g_tmpA  [(size_t)NTOT * DIM];
__device__ float g_tmpB  [(size_t)NTOT * DIM];

__device__ float2 g_cv_adj [EMAX];
__device__ float2 g_cv_id  [EMAX];
__device__ float2 g_cv_ft  [EMAX];
__device__ int    g_rp_adj [NTOT + 1];
__device__ int    g_rp_id  [NTOT + 1];
__device__ int    g_rp_ft  [NTOT + 1];
__device__ int    g_counts [NTOT + 2];
__device__ int    g_offs   [NTOT + 1];
__device__ int    g_bsums  [NB_MAX];

// ---------------- f32x2 helpers ----------------
__device__ __forceinline__ unsigned long long dup2(float x) {
    unsigned long long r;
    asm("mov.b64 %0, {%1, %1};" : "=l"(r) : "f"(x));
    return r;
}
__device__ __forceinline__ void fma2(unsigned long long& d, unsigned long long a, unsigned long long b) {
    asm("fma.rn.f32x2 %0, %1, %2, %0;" : "+l"(d) : "l"(a), "l"(b));
}
__device__ __forceinline__ float2 unpack2(unsigned long long v) {
    float2 f;
    asm("mov.b64 {%0, %1}, %2;" : "=f"(f.x), "=f"(f.y) : "l"(v));
    return f;
}

// ---------------- small utility kernels ----------------
__global__ void zero_int_kernel(int* __restrict__ p, int n) {
    int i = blockIdx.x * blockDim.x + threadIdx.x;
    if (i < n) p[i] = 0;
}

// ---------------- counting sort: hist / scan / scatter ----------------
__global__ void hist_kernel(const int* __restrict__ rows, int* __restrict__ counts, int nnz) {
    int i = blockIdx.x * blockDim.x + threadIdx.x;
    if (i < nnz) atomicAdd(&counts[rows[i]], 1);
}

__global__ void scan1_kernel(const int* __restrict__ counts, int* __restrict__ rowptr,
                             int* __restrict__ bsums, int n) {
    __shared__ int sh[SCAN_BLOCK];
    int g = blockIdx.x * SCAN_BLOCK + threadIdx.x;
    int v = (g < n) ? counts[g] : 0;
    sh[threadIdx.x] = v;
    __syncthreads();
    for (int off = 1; off < SCAN_BLOCK; off <<= 1) {
        int t = (threadIdx.x >= off) ? sh[threadIdx.x - off] : 0;
        __syncthreads();
        sh[threadIdx.x] += t;
        __syncthreads();
    }
    if (g < n) rowptr[g] = sh[threadIdx.x] - v;   // exclusive
    if (threadIdx.x == SCAN_BLOCK - 1) bsums[blockIdx.x] = sh[threadIdx.x];
}

__global__ void scan2_kernel(int* __restrict__ bsums, int nb) {
    if (blockIdx.x == 0 && threadIdx.x == 0) {
        int acc = 0;
        for (int i = 0; i < nb; i++) { int t = bsums[i]; bsums[i] = acc; acc += t; }
    }
}

__global__ void scan3_kernel(int* __restrict__ rowptr, const int* __restrict__ bsums,
                             int* __restrict__ offs, int n) {
    int g = blockIdx.x * SCAN_BLOCK + threadIdx.x;
    if (g < n) {
        int v = rowptr[g] + bsums[blockIdx.x];
        rowptr[g] = v;
        offs[g] = v;
    }
}

__global__ void scatter_kernel(const int* __restrict__ rows, const int* __restrict__ cols,
                               const float* __restrict__ vals, int* __restrict__ offs,
                               float2* __restrict__ cv, int nnz) {
    int i = blockIdx.x * blockDim.x + threadIdx.x;
    if (i >= nnz) return;
    int r = rows[i];
    int pos = atomicAdd(&offs[r], 1);
    cv[pos] = make_float2(__int_as_float(cols[i]), vals[i]);
}

// ---------------- GEMM: C = (acc? C:0) + w * leaky_relu(A @ B), via FFMA2 ----------------
// A: M x K row-major, B: K x 128 row-major, C: M x 128. BM=128, BN=128, BK=16, 256 thr, 8x8/thr.
__global__ __launch_bounds__(256) void gemm_lrelu_kernel(
    const float* __restrict__ A, const float* __restrict__ B,
    float* __restrict__ C, int M, int K,
    const float* __restrict__ mw, int widx, int accumulate)
{
    __shared__ float As[16][128];   // [k][m]
    __shared__ float Bs[16][128];   // [k][n]

    int tid = threadIdx.x;
    int tx = tid & 15;              // 16 col-groups of 8
    int ty = tid >> 4;              // 16 row-groups of 8
    int blockRow = blockIdx.x * 128;

    unsigned long long acc[8][4];
#pragma unroll
    for (int i = 0; i < 8; i++)
#pragma unroll
        for (int j = 0; j < 4; j++) acc[i][j] = 0ULL;

    int arow = tid >> 1;            // 0..127
    int acol = (tid & 1) * 8;       // 0 or 8
    int brow = tid >> 5;            // 0..7 (+8)
    int bcol = (tid & 31) * 4;

    for (int k0 = 0; k0 < K; k0 += 16) {
        int gm = blockRow + arow;
        float4 av0 = make_float4(0.f, 0.f, 0.f, 0.f);
        float4 av1 = make_float4(0.f, 0.f, 0.f, 0.f);
        if (gm < M) {
            const float* ap = A + (size_t)gm * K + k0 + acol;
            av0 = *(const float4*)(ap);
            av1 = *(const float4*)(ap + 4);
        }
        As[acol + 0][arow] = av0.x;  As[acol + 1][arow] = av0.y;
        As[acol + 2][arow] = av0.z;  As[acol + 3][arow] = av0.w;
        As[acol + 4][arow] = av1.x;  As[acol + 5][arow] = av1.y;
        As[acol + 6][arow] = av1.z;  As[acol + 7][arow] = av1.w;
#pragma unroll
        for (int r = 0; r < 2; r++) {
            float4 bv = *(const float4*)(B + (size_t)(k0 + brow + r * 8) * 128 + bcol);
            *(float4*)&Bs[brow + r * 8][bcol] = bv;
        }
        __syncthreads();
#pragma unroll
        for (int kk = 0; kk < 16; kk++) {
            float4 a0 = *(float4*)&As[kk][ty * 8];
            float4 a1 = *(float4*)&As[kk][ty * 8 + 4];
            unsigned long long b[4];
#pragma unroll
            for (int j = 0; j < 4; j++)
                b[j] = *(unsigned long long*)&Bs[kk][tx * 8 + 2 * j];
            unsigned long long ad[8];
            ad[0] = dup2(a0.x); ad[1] = dup2(a0.y); ad[2] = dup2(a0.z); ad[3] = dup2(a0.w);
            ad[4] = dup2(a1.x); ad[5] = dup2(a1.y); ad[6] = dup2(a1.z); ad[7] = dup2(a1.w);
#pragma unroll
            for (int i = 0; i < 8; i++)
#pragma unroll
                for (int j = 0; j < 4; j++)
                    fma2(acc[i][j], ad[i], b[j]);
        }
        __syncthreads();
    }

    // softmax(modal_weight)[widx]
    float m0 = mw[0], m1 = mw[1];
    float mx = fmaxf(m0, m1);
    float e0 = __expf(m0 - mx), e1 = __expf(m1 - mx);
    float w = ((widx == 0) ? e0 : e1) / (e0 + e1);

#pragma unroll
    for (int i = 0; i < 8; i++) {
        int gm = blockRow + ty * 8 + i;
        if (gm >= M) continue;
        float* crow = C + (size_t)gm * 128 + tx * 8;
#pragma unroll
        for (int j = 0; j < 4; j++) {
            float2 f = unpack2(acc[i][j]);
            float vx = (f.x > 0.f) ? f.x : 0.2f * f.x;
            float vy = (f.y > 0.f) ? f.y : 0.2f * f.y;
            vx *= w; vy *= w;
            if (accumulate) { crow[2 * j] += vx; crow[2 * j + 1] += vy; }
            else            { crow[2 * j]  = vx; crow[2 * j + 1]  = vy; }
        }
    }
}

// ---------------- row-wise L2 normalize in place (warp per row, DIM=128) ----------------
__global__ void l2norm_rows_kernel(float* __restrict__ x, int nrows)
{
    int wid = (blockIdx.x * blockDim.x + threadIdx.x) >> 5;
    int lane = threadIdx.x & 31;
    if (wid >= nrows) return;
    float4* p = (float4*)(x + (size_t)wid * DIM) + lane;
    float4 v = *p;
    float s = v.x * v.x + v.y * v.y + v.z * v.z + v.w * v.w;
#pragma unroll
    for (int o = 16; o > 0; o >>= 1) s += __shfl_xor_sync(0xffffffffu, s, o);
    float inv = 1.f / fmaxf(sqrtf(s), 1e-12f);
    v.x *= inv; v.y *= inv; v.z *= inv; v.w *= inv;
    *p = v;
}

// ---------------- CSR gather SpMM (warp per row) ----------------
__device__ __forceinline__ float4 gfetch(float2 c, int lane,
                                         const float* __restrict__ xU,
                                         const float* __restrict__ xI) {
    int col = __float_as_int(c.x);
    const float* x = (col < USERS) ? (xU + (size_t)col * DIM)
                                   : (xI + (size_t)(col - USERS) * DIM);
    return __ldg((const float4*)x + lane);
}

__global__ void spmm_csr_kernel(const int* __restrict__ rowptr, const float2* __restrict__ cv,
                                const float* __restrict__ xU, const float* __restrict__ xI,
                                float* __restrict__ out)
{
    int row = blockIdx.x * 8 + (threadIdx.x >> 5);
    int lane = threadIdx.x & 31;
    if (row >= NTOT) return;
    int s = rowptr[row], e = rowptr[row + 1];
    float4 acc = make_float4(0.f, 0.f, 0.f, 0.f);
    int i = s;
    for (; i + 2 <= e; i += 2) {
        float2 c0 = cv[i], c1 = cv[i + 1];
        float4 x0 = gfetch(c0, lane, xU, xI);
        float4 x1 = gfetch(c1, lane, xU, xI);
        acc.x += c0.y * x0.x + c1.y * x1.x;
        acc.y += c0.y * x0.y + c1.y * x1.y;
        acc.z += c0.y * x0.z + c1.y * x1.z;
        acc.w += c0.y * x0.w + c1.y * x1.w;
    }
    if (i < e) {
        float2 c0 = cv[i];
        float4 x0 = gfetch(c0, lane, xU, xI);
        acc.x += c0.y * x0.x; acc.y += c0.y * x0.y;
        acc.z += c0.y * x0.z; acc.w += c0.y * x0.w;
    }
    *((float4*)(out + (size_t)row * DIM) + lane) = acc;
}

// Dual SpMM, shared USER table: outA uses (xU, xIa), outB uses (xU, xIb).
__global__ void spmm_csr_dualU_kernel(const int* __restrict__ rowptr, const float2* __restrict__ cv,
                                      const float* __restrict__ xU,
                                      const float* __restrict__ xIa, const float* __restrict__ xIb,
                                      float* __restrict__ outA, float* __restrict__ outB)
{
    int row = blockIdx.x * 8 + (threadIdx.x >> 5);
    int lane = threadIdx.x & 31;
    if (row >= NTOT) return;
    int s = rowptr[row], e = rowptr[row + 1];
    float4 accA = make_float4(0.f, 0.f, 0.f, 0.f);
    float4 accB = make_float4(0.f, 0.f, 0.f, 0.f);
    for (int i = s; i < e; i++) {
        float2 c = cv[i];
        int col = __float_as_int(c.x);
        float4 xa, xb;
        if (col < USERS) {
            xa = __ldg((const float4*)(xU + (size_t)col * DIM) + lane);
            xb = xa;
        } else {
            size_t off = (size_t)(col - USERS) * DIM;
            xa = __ldg((const float4*)(xIa + off) + lane);
            xb = __ldg((const float4*)(xIb + off) + lane);
        }
        accA.x += c.y * xa.x; accA.y += c.y * xa.y; accA.z += c.y * xa.z; accA.w += c.y * xa.w;
        accB.x += c.y * xb.x; accB.y += c.y * xb.y; accB.z += c.y * xb.z; accB.w += c.y * xb.w;
    }
    *((float4*)(outA + (size_t)row * DIM) + lane) = accA;
    *((float4*)(outB + (size_t)row * DIM) + lane) = accB;
}

// Dual SpMM, shared ITEM table: outA uses (xUa, xI), outB uses (xUb, xI).
__global__ void spmm_csr_dualI_kernel(const int* __restrict__ rowptr, const float2* __restrict__ cv,
                                      const float* __restrict__ xUa, const float* __restrict__ xUb,
                                      const float* __restrict__ xI,
                                      float* __restrict__ outA, float* __restrict__ outB)
{
    int row = blockIdx.x * 8 + (threadIdx.x >> 5);
    int lane = threadIdx.x & 31;
    if (row >= NTOT) return;
    int s = rowptr[row], e = rowptr[row + 1];
    float4 accA = make_float4(0.f, 0.f, 0.f, 0.f);
    float4 accB = make_float4(0.f, 0.f, 0.f, 0.f);
    for (int i = s; i < e; i++) {
        float2 c = cv[i];
        int col = __float_as_int(c.x);
        float4 xa, xb;
        if (col < USERS) {
            size_t off = (size_t)col * DIM;
            xa = __ldg((const float4*)(xUa + off) + lane);
            xb = __ldg((const float4*)(xUb + off) + lane);
        } else {
            xa = __ldg((const float4*)(xI + (size_t)(col - USERS) * DIM) + lane);
            xb = xa;
        }
        accA.x += c.y * xa.x; accA.y += c.y * xa.y; accA.z += c.y * xa.z; accA.w += c.y * xa.w;
        accB.x += c.y * xb.x; accB.y += c.y * xb.y; accB.z += c.y * xb.z; accB.w += c.y * xb.w;
    }
    *((float4*)(outA + (size_t)row * DIM) + lane) = accA;
    *((float4*)(outB + (size_t)row * DIM) + lane) = accB;
}

// ---------------- combine: modal = 0.5*(Id+Id2+0.2*IdAdj) + 0.5*(Ft+Ft2+0.2*FtAdj) ----------------
__global__ void combine_kernel(const float4* __restrict__ id, const float4* __restrict__ id2,
                               const float4* __restrict__ idadj,
                               const float4* __restrict__ ft, const float4* __restrict__ ft2,
                               const float4* __restrict__ ftadj,
                               float4* __restrict__ modal, int n4)
{
    int i = blockIdx.x * blockDim.x + threadIdx.x;
    if (i >= n4) return;
    float4 a = id[i], b = id2[i], c = idadj[i];
    float4 d = ft[i], e = ft2[i], f = ftadj[i];
    float4 m;
    m.x = 0.5f * (a.x + b.x + 0.2f * c.x) + 0.5f * (d.x + e.x + 0.2f * f.x);
    m.y = 0.5f * (a.y + b.y + 0.2f * c.y) + 0.5f * (d.y + e.y + 0.2f * f.y);
    m.z = 0.5f * (a.z + b.z + 0.2f * c.z) + 0.5f * (d.z + e.z + 0.2f * f.z);
    m.w = 0.5f * (a.w + b.w + 0.2f * c.w) + 0.5f * (d.w + e.w + 0.2f * f.w);
    modal[i] = m;
}

// ---------------- final: out = modal + A + B + 0.5 * l2norm(modal)  (warp per row) ----------------
__global__ void final_kernel(const float* __restrict__ modal, const float* __restrict__ A,
                             const float* __restrict__ B, float* __restrict__ out, int nrows)
{
    int wid = (blockIdx.x * blockDim.x + threadIdx.x) >> 5;
    int lane = threadIdx.x & 31;
    if (wid >= nrows) return;
    size_t off = (size_t)wid * DIM + lane * 4;
    float4 m = *(const float4*)(modal + off);
    float4 a = *(const float4*)(A + off);
    float4 b = *(const float4*)(B + off);
    float s = m.x * m.x + m.y * m.y + m.z * m.z + m.w * m.w;
#pragma unroll
    for (int o = 16; o > 0; o >>= 1) s += __shfl_xor_sync(0xffffffffu, s, o);
    float inv = 0.5f / fmaxf(sqrtf(s), 1e-12f);   // RIS_LAMBDA / norm
    float4 r;
    r.x = m.x + a.x + b.x + inv * m.x;
    r.y = m.y + a.y + b.y + inv * m.y;
    r.z = m.z + a.z + b.z + inv * m.z;
    r.w = m.w + a.w + b.w + inv * m.w;
    *(float4*)(out + off) = r;
}

// ---------------- host ----------------
static void build_csr(const int* rows, const int* cols, const float* vals, int nnz,
                      int* counts, int* bsums, int* offs, int* rowptr, float2* cv)
{
    int n = NTOT + 1;
    int nb = (n + SCAN_BLOCK - 1) / SCAN_BLOCK;
    zero_int_kernel<<<(n + 255) / 256, 256>>>(counts, n);
    hist_kernel<<<(nnz + 255) / 256, 256>>>(rows, counts, nnz);
    scan1_kernel<<<nb, SCAN_BLOCK>>>(counts, rowptr, bsums, n);
    scan2_kernel<<<1, 32>>>(bsums, nb);
    scan3_kernel<<<nb, SCAN_BLOCK>>>(rowptr, bsums, offs, n);
    scatter_kernel<<<(nnz + 255) / 256, 256>>>(rows, cols, vals, offs, cv, nnz);
}

extern "C" void kernel_launch(void* const* d_in, const int* in_sizes, int n_in,
                              void* d_out, int out_size)
{
    const int*   adj_rows = (const int*)d_in[0];
    const int*   adj_cols = (const int*)d_in[1];
    const float* adj_vals = (const float*)d_in[2];
    const int*   id_rows  = (const int*)d_in[3];
    const int*   id_cols  = (const int*)d_in[4];
    const float* id_vals  = (const float*)d_in[5];
    const int*   ft_rows  = (const int*)d_in[6];
    const int*   ft_cols  = (const int*)d_in[7];
    const float* ft_vals  = (const float*)d_in[8];
    const float* uEmb     = (const float*)d_in[9];
    const float* iEmb     = (const float*)d_in[10];
    const float* img_emb  = (const float*)d_in[11];
    const float* img_id   = (const float*)d_in[12];
    const float* txt_emb  = (const float*)d_in[13];
    const float* txt_id   = (const float*)d_in[14];
    const float* img_tr   = (const float*)d_in[15];
    const float* img_id_tr= (const float*)d_in[16];
    const float* txt_tr   = (const float*)d_in[17];
    const float* txt_id_tr= (const float*)d_in[18];
    const float* mw       = (const float*)d_in[19];
    float* out = (float*)d_out;

    int E_adj = in_sizes[0];
    int E_id  = in_sizes[3];
    int E_ft  = in_sizes[6];

    float *pAllID, *pAllFeat, *pId, *pId2, *pIdAdj, *pFt, *pFt2, *pFtAdj, *pModal, *pA, *pB;
    float2 *cvAdj, *cvId, *cvFt;
    int *rpAdj, *rpId, *rpFt, *pCounts, *pOffs, *pBsums;
    cudaGetSymbolAddress((void**)&pAllID,  g_allID);
    cudaGetSymbolAddress((void**)&pAllFeat,g_allFeat);
    cudaGetSymbolAddress((void**)&pId,     g_Id);
    cudaGetSymbolAddress((void**)&pId2,    g_Id2);
    cudaGetSymbolAddress((void**)&pIdAdj,  g_IdAdj);
    cudaGetSymbolAddress((void**)&pFt,     g_Ft);
    cudaGetSymbolAddress((void**)&pFt2,    g_Ft2);
    cudaGetSymbolAddress((void**)&pFtAdj,  g_FtAdj);
    cudaGetSymbolAddress((void**)&pModal,  g_modal);
    cudaGetSymbolAddress((void**)&pA,      g_tmpA);
    cudaGetSymbolAddress((void**)&pB,      g_tmpB);
    cudaGetSymbolAddress((void**)&cvAdj,   g_cv_adj);
    cudaGetSymbolAddress((void**)&cvId,    g_cv_id);
    cudaGetSymbolAddress((void**)&cvFt,    g_cv_ft);
    cudaGetSymbolAddress((void**)&rpAdj,   g_rp_adj);
    cudaGetSymbolAddress((void**)&rpId,    g_rp_id);
    cudaGetSymbolAddress((void**)&rpFt,    g_rp_ft);
    cudaGetSymbolAddress((void**)&pCounts, g_counts);
    cudaGetSymbolAddress((void**)&pOffs,   g_offs);
    cudaGetSymbolAddress((void**)&pBsums,  g_bsums);

    // 1) CSR-ify the three sparse matrices (counting sort, fully on-device)
    build_csr(adj_rows, adj_cols, adj_vals, E_adj, pCounts, pBsums, pOffs, rpAdj, cvAdj);
    build_csr(id_rows,  id_cols,  id_vals,  E_id,  pCounts, pBsums, pOffs, rpId,  cvId);
    build_csr(ft_rows,  ft_cols,  ft_vals,  E_ft,  pCounts, pBsums, pOffs, rpFt,  cvFt);

    // 2) modality GEMMs (FFMA2 path)
    int gemm_blocks = (ITEMS + 127) / 128;
    gemm_lrelu_kernel<<<gemm_blocks, 256>>>(img_id,  img_id_tr, pAllID,  ITEMS, 1024, mw, 0, 0);
    gemm_lrelu_kernel<<<gemm_blocks, 256>>>(txt_id,  txt_id_tr, pAllID,  ITEMS,  768, mw, 1, 1);
    gemm_lrelu_kernel<<<gemm_blocks, 256>>>(img_emb, img_tr,    pAllFeat,ITEMS, 1024, mw, 0, 0);
    gemm_lrelu_kernel<<<gemm_blocks, 256>>>(txt_emb, txt_tr,    pAllFeat,ITEMS,  768, mw, 1, 1);

    // 3) row l2-normalize item-side modality embeddings
    int l2_blocks = (ITEMS * 32 + 255) / 256;
    l2norm_rows_kernel<<<l2_blocks, 256>>>(pAllID,   ITEMS);
    l2norm_rows_kernel<<<l2_blocks, 256>>>(pAllFeat, ITEMS);

    // 4) SpMMs (gather; no zeroing needed — every row fully written)
    int spmm_blocks = (NTOT + 7) / 8;
    spmm_csr_kernel<<<spmm_blocks, 256>>>(rpId, cvId, uEmb, iEmb, pIdAdj);
    spmm_csr_kernel<<<spmm_blocks, 256>>>(rpFt, cvFt, uEmb, iEmb, pFtAdj);
    spmm_csr_dualU_kernel<<<spmm_blocks, 256>>>(rpAdj, cvAdj, uEmb, pAllID, pAllFeat, pId, pFt);
    spmm_csr_dualI_kernel<<<spmm_blocks, 256>>>(rpAdj, cvAdj, pId, pFt, iEmb, pId2, pFt2);

    // 5) combine into modal
    int n4 = (int)(((size_t)NTOT * DIM) / 4);
    combine_kernel<<<(n4 + 255) / 256, 256>>>((float4*)pId, (float4*)pId2, (float4*)pIdAdj,
                                              (float4*)pFt, (float4*)pFt2, (float4*)pFtAdj,
                                              (float4*)pModal, n4);

    // 6) 2-layer GNN propagation
    spmm_csr_kernel<<<spmm_blocks, 256>>>(rpAdj, cvAdj, pModal, pModal + (size_t)USERS * DIM, pA);
    spmm_csr_kernel<<<spmm_blocks, 256>>>(rpAdj, cvAdj, pA, pA + (size_t)USERS * DIM, pB);

    // 7) final: out = modal + A + B + 0.5 * l2norm(modal)
    int fin_blocks = (NTOT * 32 + 255) / 256;
    final_kernel<<<fin_blocks, 256>>>(pModal, pA, pB, out, NTOT);

    (void)n_in; (void)out_size;
}

// round 3
// speedup vs baseline: 3.2254x; 1.8084x over previous
#include <cuda_runtime.h>
#include <cstdint>
#include <cstddef>

#define USERS 50000
#define ITEMS 50000
#define NTOT  100000
#define DIM   128
#define EMAX  1700000
#define SCAN_BLOCK 1024
#define NB_MAX 128

// ---------------- scratch (device globals; allocation-free) ----------------
__device__ float g_allID [(size_t)ITEMS * DIM];
__device__ float g_allFeat[(size_t)ITEMS * DIM];
__device__ float g_Id    [(size_t)NTOT * DIM];
__device__ float g_Id2   [(size_t)NTOT * DIM];
__device__ float g_IdAdj [(size_t)NTOT * DIM];
__device__ float g_Ft    [(size_t)NTOT * DIM];
__device__ float g_Ft2   [(size_t)NTOT * DIM];
__device__ float g_FtAdj [(size_t)NTOT * DIM];
__device__ float g_modal [(size_t)NTOT * DIM];
__device__ float g_tmpA  [(size_t)NTOT * DIM];   // also hosts GEMM L0/L1
__device__ float g_tmpB  [(size_t)NTOT * DIM];   // also hosts GEMM L2/L3

__device__ float2 g_cv_adj [EMAX];
__device__ float2 g_cv_id  [EMAX];
__device__ float2 g_cv_ft  [EMAX];
__device__ int    g_rp_adj [NTOT + 1];
__device__ int    g_rp_id  [NTOT + 1];
__device__ int    g_rp_ft  [NTOT + 1];
__device__ int    g_counts [NTOT + 2];
__device__ int    g_offs   [NTOT + 1];
__device__ int    g_bsums  [NB_MAX];

// ---------------- small utility kernels ----------------
__global__ void zero_int_kernel(int* __restrict__ p, int n) {
    int i = blockIdx.x * blockDim.x + threadIdx.x;
    if (i < n) p[i] = 0;
}

// ---------------- counting sort: hist / scan / scatter ----------------
__global__ void hist_kernel(const int* __restrict__ rows, int* __restrict__ counts, int nnz) {
    int i = blockIdx.x * blockDim.x + threadIdx.x;
    if (i < nnz) atomicAdd(&counts[rows[i]], 1);
}

__global__ void scan1_kernel(const int* __restrict__ counts, int* __restrict__ rowptr,
                             int* __restrict__ bsums, int n) {
    __shared__ int sh[SCAN_BLOCK];
    int g = blockIdx.x * SCAN_BLOCK + threadIdx.x;
    int v = (g < n) ? counts[g] : 0;
    sh[threadIdx.x] = v;
    __syncthreads();
    for (int off = 1; off < SCAN_BLOCK; off <<= 1) {
        int t = (threadIdx.x >= off) ? sh[threadIdx.x - off] : 0;
        __syncthreads();
        sh[threadIdx.x] += t;
        __syncthreads();
    }
    if (g < n) rowptr[g] = sh[threadIdx.x] - v;   // exclusive
    if (threadIdx.x == SCAN_BLOCK - 1) bsums[blockIdx.x] = sh[threadIdx.x];
}

__global__ void scan2_kernel(int* __restrict__ bsums, int nb) {
    if (blockIdx.x == 0 && threadIdx.x == 0) {
        int acc = 0;
        for (int i = 0; i < nb; i++) { int t = bsums[i]; bsums[i] = acc; acc += t; }
    }
}

__global__ void scan3_kernel(int* __restrict__ rowptr, const int* __restrict__ bsums,
                             int* __restrict__ offs, int n) {
    int g = blockIdx.x * SCAN_BLOCK + threadIdx.x;
    if (g < n) {
        int v = rowptr[g] + bsums[blockIdx.x];
        rowptr[g] = v;
        offs[g] = v;
    }
}

__global__ void scatter_kernel(const int* __restrict__ rows, const int* __restrict__ cols,
                               const float* __restrict__ vals, int* __restrict__ offs,
                               float2* __restrict__ cv, int nnz) {
    int i = blockIdx.x * blockDim.x + threadIdx.x;
    if (i >= nnz) return;
    int r = rows[i];
    int pos = atomicAdd(&offs[r], 1);
    cv[pos] = make_float2(__int_as_float(cols[i]), vals[i]);
}

// ---------------- tf32 tensor-core GEMM: L = leaky_relu(A @ B) ----------------
__device__ __forceinline__ uint32_t to_tf32(float f) {
    uint32_t r;
    asm("cvt.rna.tf32.f32 %0, %1;" : "=r"(r) : "f"(f));
    return r;
}
__device__ __forceinline__ void mma_tf32(float c[4], uint32_t a0, uint32_t a1,
                                         uint32_t a2, uint32_t a3,
                                         uint32_t b0, uint32_t b1) {
    asm volatile(
        "mma.sync.aligned.m16n8k8.row.col.f32.tf32.tf32.f32 "
        "{%0,%1,%2,%3}, {%4,%5,%6,%7}, {%8,%9}, {%0,%1,%2,%3};"
        : "+f"(c[0]), "+f"(c[1]), "+f"(c[2]), "+f"(c[3])
        : "r"(a0), "r"(a1), "r"(a2), "r"(a3), "r"(b0), "r"(b1));
}

#define AS_STRIDE 36
#define BS_STRIDE 132

// 4 GEMMs in one grid: blockIdx.y = gemm id. A: M x K row-major, B: K x 128, L: M x 128.
// Epilogue: leaky_relu only (modal weight applied downstream).
__global__ __launch_bounds__(256, 2) void gemm4_kernel(
    const float* __restrict__ A0, const float* __restrict__ A1,
    const float* __restrict__ A2, const float* __restrict__ A3,
    const float* __restrict__ B0, const float* __restrict__ B1,
    const float* __restrict__ B2, const float* __restrict__ B3,
    float* __restrict__ L0, float* __restrict__ L1,
    float* __restrict__ L2, float* __restrict__ L3)
{
    __shared__ uint32_t As[128 * AS_STRIDE];
    __shared__ uint32_t Bs[32 * BS_STRIDE];

    int g = blockIdx.y;
    const float* A = (g == 0) ? A0 : (g == 1) ? A1 : (g == 2) ? A2 : A3;
    const float* B = (g == 0) ? B0 : (g == 1) ? B1 : (g == 2) ? B2 : B3;
    float*       L = (g == 0) ? L0 : (g == 1) ? L1 : (g == 2) ? L2 : L3;
    int K = (g & 1) ? 768 : 1024;
    const int M = ITEMS;

    int tid = threadIdx.x;
    int wid = tid >> 5;
    int lane = tid & 31;
    int grp = lane >> 2;       // 0..7
    int tig = lane & 3;        // 0..3
    int warp_m = wid & 1;      // 2 warps in M -> 64 rows each
    int warp_n = wid >> 1;     // 4 warps in N -> 32 cols each
    int blockRow = blockIdx.x * 128;

    float c[4][4][4];          // [mt][nt][frag]
#pragma unroll
    for (int mt = 0; mt < 4; mt++)
#pragma unroll
        for (int nt = 0; nt < 4; nt++)
#pragma unroll
            for (int f = 0; f < 4; f++) c[mt][nt][f] = 0.f;

    for (int k0 = 0; k0 < K; k0 += 32) {
        // load A tile 128x32 -> As[m][k], tf32
#pragma unroll
        for (int t = 0; t < 4; t++) {
            int idx = tid + t * 256;
            int row = idx >> 3;
            int kq = (idx & 7) << 2;
            int gm = blockRow + row;
            float4 v = make_float4(0.f, 0.f, 0.f, 0.f);
            if (gm < M) v = *(const float4*)(A + (size_t)gm * K + k0 + kq);
            uint32_t* p = &As[row * AS_STRIDE + kq];
            p[0] = to_tf32(v.x); p[1] = to_tf32(v.y);
            p[2] = to_tf32(v.z); p[3] = to_tf32(v.w);
        }
        // load B tile 32x128 -> Bs[k][n], tf32
#pragma unroll
        for (int t = 0; t < 4; t++) {
            int idx = tid + t * 256;
            int row = idx >> 5;
            int nq = (idx & 31) << 2;
            float4 v = *(const float4*)(B + (size_t)(k0 + row) * 128 + nq);
            uint32_t* p = &Bs[row * BS_STRIDE + nq];
            p[0] = to_tf32(v.x); p[1] = to_tf32(v.y);
            p[2] = to_tf32(v.z); p[3] = to_tf32(v.w);
        }
        __syncthreads();

#pragma unroll
        for (int ks = 0; ks < 4; ks++) {
            int kb = ks * 8;
            uint32_t a[4][4];
#pragma unroll
            for (int mt = 0; mt < 4; mt++) {
                int mb = warp_m * 64 + mt * 16;
                a[mt][0] = As[(mb + grp)     * AS_STRIDE + kb + tig];
                a[mt][1] = As[(mb + grp + 8) * AS_STRIDE + kb + tig];
                a[mt][2] = As[(mb + grp)     * AS_STRIDE + kb + tig + 4];
                a[mt][3] = As[(mb + grp + 8) * AS_STRIDE + kb + tig + 4];
            }
            uint32_t b[4][2];
#pragma unroll
            for (int nt = 0; nt < 4; nt++) {
                int nb = warp_n * 32 + nt * 8;
                b[nt][0] = Bs[(kb + tig)     * BS_STRIDE + nb + grp];
                b[nt][1] = Bs[(kb + tig + 4) * BS_STRIDE + nb + grp];
            }
#pragma unroll
            for (int mt = 0; mt < 4; mt++)
#pragma unroll
                for (int nt = 0; nt < 4; nt++)
                    mma_tf32(c[mt][nt], a[mt][0], a[mt][1], a[mt][2], a[mt][3],
                             b[nt][0], b[nt][1]);
        }
        __syncthreads();
    }

    // epilogue: leaky_relu(0.2), store
#pragma unroll
    for (int mt = 0; mt < 4; mt++) {
        int row0 = blockRow + warp_m * 64 + mt * 16 + grp;
        int row1 = row0 + 8;
#pragma unroll
        for (int nt = 0; nt < 4; nt++) {
            int col = warp_n * 32 + nt * 8 + 2 * tig;
            float v0 = c[mt][nt][0], v1 = c[mt][nt][1];
            float v2 = c[mt][nt][2], v3 = c[mt][nt][3];
            v0 = (v0 > 0.f) ? v0 : 0.2f * v0;
            v1 = (v1 > 0.f) ? v1 : 0.2f * v1;
            v2 = (v2 > 0.f) ? v2 : 0.2f * v2;
            v3 = (v3 > 0.f) ? v3 : 0.2f * v3;
            if (row0 < M) *(float2*)(L + (size_t)row0 * 128 + col) = make_float2(v0, v1);
            if (row1 < M) *(float2*)(L + (size_t)row1 * 128 + col) = make_float2(v2, v3);
        }
    }
}

// ---------------- combine two lrelu buffers with softmax weights + l2norm ----------------
__global__ void combine_l2norm_kernel(const float* __restrict__ La, const float* __restrict__ Lb,
                                      const float* __restrict__ mw, float* __restrict__ out,
                                      int nrows)
{
    int wid = (blockIdx.x * blockDim.x + threadIdx.x) >> 5;
    int lane = threadIdx.x & 31;
    if (wid >= nrows) return;
    float m0 = mw[0], m1 = mw[1];
    float mx = fmaxf(m0, m1);
    float e0 = __expf(m0 - mx), e1 = __expf(m1 - mx);
    float w0 = e0 / (e0 + e1), w1 = e1 / (e0 + e1);
    size_t off = (size_t)wid * DIM + lane * 4;
    float4 a = *(const float4*)(La + off);
    float4 b = *(const float4*)(Lb + off);
    float4 v;
    v.x = w0 * a.x + w1 * b.x;
    v.y = w0 * a.y + w1 * b.y;
    v.z = w0 * a.z + w1 * b.z;
    v.w = w0 * a.w + w1 * b.w;
    float s = v.x * v.x + v.y * v.y + v.z * v.z + v.w * v.w;
#pragma unroll
    for (int o = 16; o > 0; o >>= 1) s += __shfl_xor_sync(0xffffffffu, s, o);
    float inv = 1.f / fmaxf(sqrtf(s), 1e-12f);
    v.x *= inv; v.y *= inv; v.z *= inv; v.w *= inv;
    *(float4*)(out + off) = v;
}

// ---------------- CSR gather SpMM (warp per row) ----------------
__device__ __forceinline__ float4 gfetch(float2 c, int lane,
                                         const float* __restrict__ xU,
                                         const float* __restrict__ xI) {
    int col = __float_as_int(c.x);
    const float* x = (col < USERS) ? (xU + (size_t)col * DIM)
                                   : (xI + (size_t)(col - USERS) * DIM);
    return __ldg((const float4*)x + lane);
}

__global__ void spmm_csr_kernel(const int* __restrict__ rowptr, const float2* __restrict__ cv,
                                const float* __restrict__ xU, const float* __restrict__ xI,
                                float* __restrict__ out)
{
    int row = blockIdx.x * 8 + (threadIdx.x >> 5);
    int lane = threadIdx.x & 31;
    if (row >= NTOT) return;
    int s = rowptr[row], e = rowptr[row + 1];
    float4 acc = make_float4(0.f, 0.f, 0.f, 0.f);
    int i = s;
    for (; i + 2 <= e; i += 2) {
        float2 c0 = cv[i], c1 = cv[i + 1];
        float4 x0 = gfetch(c0, lane, xU, xI);
        float4 x1 = gfetch(c1, lane, xU, xI);
        acc.x += c0.y * x0.x + c1.y * x1.x;
        acc.y += c0.y * x0.y + c1.y * x1.y;
        acc.z += c0.y * x0.z + c1.y * x1.z;
        acc.w += c0.y * x0.w + c1.y * x1.w;
    }
    if (i < e) {
        float2 c0 = cv[i];
        float4 x0 = gfetch(c0, lane, xU, xI);
        acc.x += c0.y * x0.x; acc.y += c0.y * x0.y;
        acc.z += c0.y * x0.z; acc.w += c0.y * x0.w;
    }
    *((float4*)(out + (size_t)row * DIM) + lane) = acc;
}

// Dual SpMM, shared USER table: outA uses (xU, xIa), outB uses (xU, xIb).
__global__ void spmm_csr_dualU_kernel(const int* __restrict__ rowptr, const float2* __restrict__ cv,
                                      const float* __restrict__ xU,
                                      const float* __restrict__ xIa, const float* __restrict__ xIb,
                                      float* __restrict__ outA, float* __restrict__ outB)
{
    int row = blockIdx.x * 8 + (threadIdx.x >> 5);
    int lane = threadIdx.x & 31;
    if (row >= NTOT) return;
    int s = rowptr[row], e = rowptr[row + 1];
    float4 accA = make_float4(0.f, 0.f, 0.f, 0.f);
    float4 accB = make_float4(0.f, 0.f, 0.f, 0.f);
    for (int i = s; i < e; i++) {
        float2 c = cv[i];
        int col = __float_as_int(c.x);
        float4 xa, xb;
        if (col < USERS) {
            xa = __ldg((const float4*)(xU + (size_t)col * DIM) + lane);
            xb = xa;
        } else {
            size_t off = (size_t)(col - USERS) * DIM;
            xa = __ldg((const float4*)(xIa + off) + lane);
            xb = __ldg((const float4*)(xIb + off) + lane);
        }
        accA.x += c.y * xa.x; accA.y += c.y * xa.y; accA.z += c.y * xa.z; accA.w += c.y * xa.w;
        accB.x += c.y * xb.x; accB.y += c.y * xb.y; accB.z += c.y * xb.z; accB.w += c.y * xb.w;
    }
    *((float4*)(outA + (size_t)row * DIM) + lane) = accA;
    *((float4*)(outB + (size_t)row * DIM) + lane) = accB;
}

// Dual SpMM, shared ITEM table: outA uses (xUa, xI), outB uses (xUb, xI).
__global__ void spmm_csr_dualI_kernel(const int* __restrict__ rowptr, const float2* __restrict__ cv,
                                      const float* __restrict__ xUa, const float* __restrict__ xUb,
                                      const float* __restrict__ xI,
                                      float* __restrict__ outA, float* __restrict__ outB)
{
    int row = blockIdx.x * 8 + (threadIdx.x >> 5);
    int lane = threadIdx.x & 31;
    if (row >= NTOT) return;
    int s = rowptr[row], e = rowptr[row + 1];
    float4 accA = make_float4(0.f, 0.f, 0.f, 0.f);
    float4 accB = make_float4(0.f, 0.f, 0.f, 0.f);
    for (int i = s; i < e; i++) {
        float2 c = cv[i];
        int col = __float_as_int(c.x);
        float4 xa, xb;
        if (col < USERS) {
            size_t off = (size_t)col * DIM;
            xa = __ldg((const float4*)(xUa + off) + lane);
            xb = __ldg((const float4*)(xUb + off) + lane);
        } else {
            xa = __ldg((const float4*)(xI + (size_t)(col - USERS) * DIM) + lane);
            xb = xa;
        }
        accA.x += c.y * xa.x; accA.y += c.y * xa.y; accA.z += c.y * xa.z; accA.w += c.y * xa.w;
        accB.x += c.y * xb.x; accB.y += c.y * xb.y; accB.z += c.y * xb.z; accB.w += c.y * xb.w;
    }
    *((float4*)(outA + (size_t)row * DIM) + lane) = accA;
    *((float4*)(outB + (size_t)row * DIM) + lane) = accB;
}

// ---------------- combine: modal = 0.5*(Id+Id2+0.2*IdAdj) + 0.5*(Ft+Ft2+0.2*FtAdj) ----------------
__global__ void combine_kernel(const float4* __restrict__ id, const float4* __restrict__ id2,
                               const float4* __restrict__ idadj,
                               const float4* __restrict__ ft, const float4* __restrict__ ft2,
                               const float4* __restrict__ ftadj,
                               float4* __restrict__ modal, int n4)
{
    int i = blockIdx.x * blockDim.x + threadIdx.x;
    if (i >= n4) return;
    float4 a = id[i], b = id2[i], c = idadj[i];
    float4 d = ft[i], e = ft2[i], f = ftadj[i];
    float4 m;
    m.x = 0.5f * (a.x + b.x + 0.2f * c.x) + 0.5f * (d.x + e.x + 0.2f * f.x);
    m.y = 0.5f * (a.y + b.y + 0.2f * c.y) + 0.5f * (d.y + e.y + 0.2f * f.y);
    m.z = 0.5f * (a.z + b.z + 0.2f * c.z) + 0.5f * (d.z + e.z + 0.2f * f.z);
    m.w = 0.5f * (a.w + b.w + 0.2f * c.w) + 0.5f * (d.w + e.w + 0.2f * f.w);
    modal[i] = m;
}

// ---------------- final: out = modal + A + B + 0.5 * l2norm(modal)  (warp per row) ----------------
__global__ void final_kernel(const float* __restrict__ modal, const float* __restrict__ A,
                             const float* __restrict__ B, float* __restrict__ out, int nrows)
{
    int wid = (blockIdx.x * blockDim.x + threadIdx.x) >> 5;
    int lane = threadIdx.x & 31;
    if (wid >= nrows) return;
    size_t off = (size_t)wid * DIM + lane * 4;
    float4 m = *(const float4*)(modal + off);
    float4 a = *(const float4*)(A + off);
    float4 b = *(const float4*)(B + off);
    float s = m.x * m.x + m.y * m.y + m.z * m.z + m.w * m.w;
#pragma unroll
    for (int o = 16; o > 0; o >>= 1) s += __shfl_xor_sync(0xffffffffu, s, o);
    float inv = 0.5f / fmaxf(sqrtf(s), 1e-12f);   // RIS_LAMBDA / norm
    float4 r;
    r.x = m.x + a.x + b.x + inv * m.x;
    r.y = m.y + a.y + b.y + inv * m.y;
    r.z = m.z + a.z + b.z + inv * m.z;
    r.w = m.w + a.w + b.w + inv * m.w;
    *(float4*)(out + off) = r;
}

// ---------------- host ----------------
static void build_csr(const int* rows, const int* cols, const float* vals, int nnz,
                      int* counts, int* bsums, int* offs, int* rowptr, float2* cv)
{
    int n = NTOT + 1;
    int nb = (n + SCAN_BLOCK - 1) / SCAN_BLOCK;
    zero_int_kernel<<<(n + 255) / 256, 256>>>(counts, n);
    hist_kernel<<<(nnz + 255) / 256, 256>>>(rows, counts, nnz);
    scan1_kernel<<<nb, SCAN_BLOCK>>>(counts, rowptr, bsums, n);
    scan2_kernel<<<1, 32>>>(bsums, nb);
    scan3_kernel<<<nb, SCAN_BLOCK>>>(rowptr, bsums, offs, n);
    scatter_kernel<<<(nnz + 255) / 256, 256>>>(rows, cols, vals, offs, cv, nnz);
}

extern "C" void kernel_launch(void* const* d_in, const int* in_sizes, int n_in,
                              void* d_out, int out_size)
{
    const int*   adj_rows = (const int*)d_in[0];
    const int*   adj_cols = (const int*)d_in[1];
    const float* adj_vals = (const float*)d_in[2];
    const int*   id_rows  = (const int*)d_in[3];
    const int*   id_cols  = (const int*)d_in[4];
    const float* id_vals  = (const float*)d_in[5];
    const int*   ft_rows  = (const int*)d_in[6];
    const int*   ft_cols  = (const int*)d_in[7];
    const float* ft_vals  = (const float*)d_in[8];
    const float* uEmb     = (const float*)d_in[9];
    const float* iEmb     = (const float*)d_in[10];
    const float* img_emb  = (const float*)d_in[11];
    const float* img_id   = (const float*)d_in[12];
    const float* txt_emb  = (const float*)d_in[13];
    const float* txt_id   = (const float*)d_in[14];
    const float* img_tr   = (const float*)d_in[15];
    const float* img_id_tr= (const float*)d_in[16];
    const float* txt_tr   = (const float*)d_in[17];
    const float* txt_id_tr= (const float*)d_in[18];
    const float* mw       = (const float*)d_in[19];
    float* out = (float*)d_out;

    int E_adj = in_sizes[0];
    int E_id  = in_sizes[3];
    int E_ft  = in_sizes[6];

    float *pAllID, *pAllFeat, *pId, *pId2, *pIdAdj, *pFt, *pFt2, *pFtAdj, *pModal, *pA, *pB;
    float2 *cvAdj, *cvId, *cvFt;
    int *rpAdj, *rpId, *rpFt, *pCounts, *pOffs, *pBsums;
    cudaGetSymbolAddress((void**)&pAllID,  g_allID);
    cudaGetSymbolAddress((void**)&pAllFeat,g_allFeat);
    cudaGetSymbolAddress((void**)&pId,     g_Id);
    cudaGetSymbolAddress((void**)&pId2,    g_Id2);
    cudaGetSymbolAddress((void**)&pIdAdj,  g_IdAdj);
    cudaGetSymbolAddress((void**)&pFt,     g_Ft);
    cudaGetSymbolAddress((void**)&pFt2,    g_Ft2);
    cudaGetSymbolAddress((void**)&pFtAdj,  g_FtAdj);
    cudaGetSymbolAddress((void**)&pModal,  g_modal);
    cudaGetSymbolAddress((void**)&pA,      g_tmpA);
    cudaGetSymbolAddress((void**)&pB,      g_tmpB);
    cudaGetSymbolAddress((void**)&cvAdj,   g_cv_adj);
    cudaGetSymbolAddress((void**)&cvId,    g_cv_id);
    cudaGetSymbolAddress((void**)&cvFt,    g_cv_ft);
    cudaGetSymbolAddress((void**)&rpAdj,   g_rp_adj);
    cudaGetSymbolAddress((void**)&rpId,    g_rp_id);
    cudaGetSymbolAddress((void**)&rpFt,    g_rp_ft);
    cudaGetSymbolAddress((void**)&pCounts, g_counts);
    cudaGetSymbolAddress((void**)&pOffs,   g_offs);
    cudaGetSymbolAddress((void**)&pBsums,  g_bsums);

    // GEMM lrelu buffers live in g_tmpA/g_tmpB (free until step 6)
    float* L_imgid = pA;
    float* L_txtid = pA + (size_t)ITEMS * DIM;
    float* L_img   = pB;
    float* L_txt   = pB + (size_t)ITEMS * DIM;

    // 1) CSR-ify the three sparse matrices (counting sort, fully on-device)
    build_csr(adj_rows, adj_cols, adj_vals, E_adj, pCounts, pBsums, pOffs, rpAdj, cvAdj);
    build_csr(id_rows,  id_cols,  id_vals,  E_id,  pCounts, pBsums, pOffs, rpId,  cvId);
    build_csr(ft_rows,  ft_cols,  ft_vals,  E_ft,  pCounts, pBsums, pOffs, rpFt,  cvFt);

    // 2) all four modality GEMMs in one launch (tf32 tensor cores)
    dim3 ggrid((ITEMS + 127) / 128, 4);
    gemm4_kernel<<<ggrid, 256>>>(img_id, txt_id, img_emb, txt_emb,
                                 img_id_tr, txt_id_tr, img_tr, txt_tr,
                                 L_imgid, L_txtid, L_img, L_txt);

    // 3) weighted combine + l2norm
    int l2_blocks = (ITEMS * 32 + 255) / 256;
    combine_l2norm_kernel<<<l2_blocks, 256>>>(L_imgid, L_txtid, mw, pAllID,   ITEMS);
    combine_l2norm_kernel<<<l2_blocks, 256>>>(L_img,   L_txt,   mw, pAllFeat, ITEMS);

    // 4) SpMMs (gather)
    int spmm_blocks = (NTOT + 7) / 8;
    spmm_csr_kernel<<<spmm_blocks, 256>>>(rpId, cvId, uEmb, iEmb, pIdAdj);
    spmm_csr_kernel<<<spmm_blocks, 256>>>(rpFt, cvFt, uEmb, iEmb, pFtAdj);
    spmm_csr_dualU_kernel<<<spmm_blocks, 256>>>(rpAdj, cvAdj, uEmb, pAllID, pAllFeat, pId, pFt);
    spmm_csr_dualI_kernel<<<spmm_blocks, 256>>>(rpAdj, cvAdj, pId, pFt, iEmb, pId2, pFt2);

    // 5) combine into modal
    int n4 = (int)(((size_t)NTOT * DIM) / 4);
    combine_kernel<<<(n4 + 255) / 256, 256>>>((float4*)pId, (float4*)pId2, (float4*)pIdAdj,
                                              (float4*)pFt, (float4*)pFt2, (float4*)pFtAdj,
                                              (float4*)pModal, n4);

    // 6) 2-layer GNN propagation (overwrites g_tmpA/g_tmpB; GEMM buffers already consumed)
    spmm_csr_kernel<<<spmm_blocks, 256>>>(rpAdj, cvAdj, pModal, pModal + (size_t)USERS * DIM, pA);
    spmm_csr_kernel<<<spmm_blocks, 256>>>(rpAdj, cvAdj, pA, pA + (size_t)USERS * DIM, pB);

    // 7) final: out = modal + A + B + 0.5 * l2norm(modal)
    int fin_blocks = (NTOT * 32 + 255) / 256;
    final_kernel<<<fin_blocks, 256>>>(pModal, pA, pB, out, NTOT);

    (void)n_in; (void)out_size;
}

// round 4
// speedup vs baseline: 3.5126x; 1.0890x over previous
#include <cuda_runtime.h>
#include <cuda_fp16.h>
#include <cstdint>
#include <cstddef>

#define USERS 50000
#define ITEMS 50000
#define NTOT  100000
#define DIM   128
#define H2ROW 64                 // half2 per row
#define EMAX  1700000
#define SCAN_BLOCK 1024
#define NB_MAX 512
#define NSEG  (NTOT + 1)

// ---------------- scratch (device globals; allocation-free) ----------------
__device__ float g_allID [(size_t)ITEMS * DIM];
__device__ float g_allFeat[(size_t)ITEMS * DIM];
__device__ float g_Id    [(size_t)NTOT * DIM];
__device__ float g_Id2   [(size_t)NTOT * DIM];
__device__ float g_IdAdj [(size_t)NTOT * DIM];
__device__ float g_Ft    [(size_t)NTOT * DIM];
__device__ float g_Ft2   [(size_t)NTOT * DIM];
__device__ float g_FtAdj [(size_t)NTOT * DIM];
__device__ float g_modal [(size_t)NTOT * DIM];
__device__ float g_tmpA  [(size_t)NTOT * DIM];   // also hosts GEMM L0/L1
__device__ float g_tmpB  [(size_t)NTOT * DIM];   // also hosts GEMM L2/L3

// fp16 gather tables
__device__ __half g_h_u     [(size_t)USERS * DIM];
__device__ __half g_h_i     [(size_t)ITEMS * DIM];
__device__ __half g_h_allID [(size_t)ITEMS * DIM];
__device__ __half g_h_allFt [(size_t)ITEMS * DIM];
__device__ __half g_h_Id    [(size_t)NTOT * DIM];
__device__ __half g_h_Ft    [(size_t)NTOT * DIM];
__device__ __half g_h_modal [(size_t)NTOT * DIM];
__device__ __half g_h_A     [(size_t)NTOT * DIM];

// batched CSR for 3 matrices (concatenated)
__device__ float2 g_cv_all [3 * EMAX];
__device__ int    g_rp     [3 * NSEG];
__device__ int    g_counts [3 * NSEG];
__device__ int    g_offs   [3 * NSEG];
__device__ int    g_bsums  [NB_MAX];

// ---------------- small utility kernels ----------------
__global__ void zero_int_kernel(int* __restrict__ p, int n) {
    int i = blockIdx.x * blockDim.x + threadIdx.x;
    if (i < n) p[i] = 0;
}

// convert fp32 table -> fp16 table
__global__ void f2h_kernel(const float4* __restrict__ in, uint2* __restrict__ outh, int n4) {
    int i = blockIdx.x * blockDim.x + threadIdx.x;
    if (i >= n4) return;
    float4 v = in[i];
    __half2 h0 = __floats2half2_rn(v.x, v.y);
    __half2 h1 = __floats2half2_rn(v.z, v.w);
    uint2 r;
    r.x = *reinterpret_cast<uint32_t*>(&h0);
    r.y = *reinterpret_cast<uint32_t*>(&h1);
    outh[i] = r;
}

// ---------------- batched counting sort: hist / scan / scatter ----------------
__global__ void hist3_kernel(const int* __restrict__ r0, const int* __restrict__ r1,
                             const int* __restrict__ r2, int n0, int n1, int n2,
                             int* __restrict__ counts) {
    int i = blockIdx.x * blockDim.x + threadIdx.x;
    int nt = n0 + n1 + n2;
    if (i >= nt) return;
    int row, seg;
    if (i < n0)            { seg = 0; row = r0[i]; }
    else if (i < n0 + n1)  { seg = 1; row = r1[i - n0]; }
    else                   { seg = 2; row = r2[i - n0 - n1]; }
    atomicAdd(&counts[seg * NSEG + row], 1);
}

__global__ void scan1_kernel(const int* __restrict__ counts, int* __restrict__ rowptr,
                             int* __restrict__ bsums, int n) {
    __shared__ int sh[SCAN_BLOCK];
    int g = blockIdx.x * SCAN_BLOCK + threadIdx.x;
    int v = (g < n) ? counts[g] : 0;
    sh[threadIdx.x] = v;
    __syncthreads();
    for (int off = 1; off < SCAN_BLOCK; off <<= 1) {
        int t = (threadIdx.x >= off) ? sh[threadIdx.x - off] : 0;
        __syncthreads();
        sh[threadIdx.x] += t;
        __syncthreads();
    }
    if (g < n) rowptr[g] = sh[threadIdx.x] - v;   // exclusive
    if (threadIdx.x == SCAN_BLOCK - 1) bsums[blockIdx.x] = sh[threadIdx.x];
}

__global__ void scan2_kernel(int* __restrict__ bsums, int nb) {
    __shared__ int sh[NB_MAX];
    int v = (threadIdx.x < nb) ? bsums[threadIdx.x] : 0;
    sh[threadIdx.x] = v;
    __syncthreads();
    for (int off = 1; off < NB_MAX; off <<= 1) {
        int t = (threadIdx.x >= off) ? sh[threadIdx.x - off] : 0;
        __syncthreads();
        sh[threadIdx.x] += t;
        __syncthreads();
    }
    if (threadIdx.x < nb) bsums[threadIdx.x] = sh[threadIdx.x] - v;  // exclusive
}

__global__ void scan3_kernel(int* __restrict__ rowptr, const int* __restrict__ bsums,
                             int* __restrict__ offs, int n) {
    int g = blockIdx.x * SCAN_BLOCK + threadIdx.x;
    if (g < n) {
        int v = rowptr[g] + bsums[blockIdx.x];
        rowptr[g] = v;
        offs[g] = v;
    }
}

__global__ void scatter3_kernel(const int* __restrict__ r0, const int* __restrict__ c0, const float* __restrict__ v0,
                                const int* __restrict__ r1, const int* __restrict__ c1, const float* __restrict__ v1,
                                const int* __restrict__ r2, const int* __restrict__ c2, const float* __restrict__ v2,
                                int n0, int n1, int n2,
                                int* __restrict__ offs, float2* __restrict__ cv) {
    int i = blockIdx.x * blockDim.x + threadIdx.x;
    int nt = n0 + n1 + n2;
    if (i >= nt) return;
    int row, seg, col; float val;
    if (i < n0)           { seg = 0; int j = i;            row = r0[j]; col = c0[j]; val = v0[j]; }
    else if (i < n0 + n1) { seg = 1; int j = i - n0;       row = r1[j]; col = c1[j]; val = v1[j]; }
    else                  { seg = 2; int j = i - n0 - n1;  row = r2[j]; col = c2[j]; val = v2[j]; }
    int pos = atomicAdd(&offs[seg * NSEG + row], 1);
    cv[pos] = make_float2(__int_as_float(col), val);
}

// ---------------- tf32 tensor-core GEMM: L = leaky_relu(A @ B) ----------------
__device__ __forceinline__ uint32_t to_tf32(float f) {
    uint32_t r;
    asm("cvt.rna.tf32.f32 %0, %1;" : "=r"(r) : "f"(f));
    return r;
}
__device__ __forceinline__ void mma_tf32(float c[4], uint32_t a0, uint32_t a1,
                                         uint32_t a2, uint32_t a3,
                                         uint32_t b0, uint32_t b1) {
    asm volatile(
        "mma.sync.aligned.m16n8k8.row.col.f32.tf32.tf32.f32 "
        "{%0,%1,%2,%3}, {%4,%5,%6,%7}, {%8,%9}, {%0,%1,%2,%3};"
        : "+f"(c[0]), "+f"(c[1]), "+f"(c[2]), "+f"(c[3])
        : "r"(a0), "r"(a1), "r"(a2), "r"(a3), "r"(b0), "r"(b1));
}

#define AS_STRIDE 36
#define BS_STRIDE 132

__global__ __launch_bounds__(256, 2) void gemm4_kernel(
    const float* __restrict__ A0, const float* __restrict__ A1,
    const float* __restrict__ A2, const float* __restrict__ A3,
    const float* __restrict__ B0, const float* __restrict__ B1,
    const float* __restrict__ B2, const float* __restrict__ B3,
    float* __restrict__ L0, float* __restrict__ L1,
    float* __restrict__ L2, float* __restrict__ L3)
{
    __shared__ uint32_t As[128 * AS_STRIDE];
    __shared__ uint32_t Bs[32 * BS_STRIDE];

    int g = blockIdx.y;
    const float* A = (g == 0) ? A0 : (g == 1) ? A1 : (g == 2) ? A2 : A3;
    const float* B = (g == 0) ? B0 : (g == 1) ? B1 : (g == 2) ? B2 : B3;
    float*       L = (g == 0) ? L0 : (g == 1) ? L1 : (g == 2) ? L2 : L3;
    int K = (g & 1) ? 768 : 1024;
    const int M = ITEMS;

    int tid = threadIdx.x;
    int wid = tid >> 5;
    int lane = tid & 31;
    int grp = lane >> 2;
    int tig = lane & 3;
    int warp_m = wid & 1;
    int warp_n = wid >> 1;
    int blockRow = blockIdx.x * 128;

    float c[4][4][4];
#pragma unroll
    for (int mt = 0; mt < 4; mt++)
#pragma unroll
        for (int nt = 0; nt < 4; nt++)
#pragma unroll
            for (int f = 0; f < 4; f++) c[mt][nt][f] = 0.f;

    for (int k0 = 0; k0 < K; k0 += 32) {
#pragma unroll
        for (int t = 0; t < 4; t++) {
            int idx = tid + t * 256;
            int row = idx >> 3;
            int kq = (idx & 7) << 2;
            int gm = blockRow + row;
            float4 v = make_float4(0.f, 0.f, 0.f, 0.f);
            if (gm < M) v = *(const float4*)(A + (size_t)gm * K + k0 + kq);
            uint32_t* p = &As[row * AS_STRIDE + kq];
            p[0] = to_tf32(v.x); p[1] = to_tf32(v.y);
            p[2] = to_tf32(v.z); p[3] = to_tf32(v.w);
        }
#pragma unroll
        for (int t = 0; t < 4; t++) {
            int idx = tid + t * 256;
            int row = idx >> 5;
            int nq = (idx & 31) << 2;
            float4 v = *(const float4*)(B + (size_t)(k0 + row) * 128 + nq);
            uint32_t* p = &Bs[row * BS_STRIDE + nq];
            p[0] = to_tf32(v.x); p[1] = to_tf32(v.y);
            p[2] = to_tf32(v.z); p[3] = to_tf32(v.w);
        }
        __syncthreads();

#pragma unroll
        for (int ks = 0; ks < 4; ks++) {
            int kb = ks * 8;
            uint32_t a[4][4];
#pragma unroll
            for (int mt = 0; mt < 4; mt++) {
                int mb = warp_m * 64 + mt * 16;
                a[mt][0] = As[(mb + grp)     * AS_STRIDE + kb + tig];
                a[mt][1] = As[(mb + grp + 8) * AS_STRIDE + kb + tig];
                a[mt][2] = As[(mb + grp)     * AS_STRIDE + kb + tig + 4];
                a[mt][3] = As[(mb + grp + 8) * AS_STRIDE + kb + tig + 4];
            }
            uint32_t b[4][2];
#pragma unroll
            for (int nt = 0; nt < 4; nt++) {
                int nb = warp_n * 32 + nt * 8;
                b[nt][0] = Bs[(kb + tig)     * BS_STRIDE + nb + grp];
                b[nt][1] = Bs[(kb + tig + 4) * BS_STRIDE + nb + grp];
            }
#pragma unroll
            for (int mt = 0; mt < 4; mt++)
#pragma unroll
                for (int nt = 0; nt < 4; nt++)
                    mma_tf32(c[mt][nt], a[mt][0], a[mt][1], a[mt][2], a[mt][3],
                             b[nt][0], b[nt][1]);
        }
        __syncthreads();
    }

#pragma unroll
    for (int mt = 0; mt < 4; mt++) {
        int row0 = blockRow + warp_m * 64 + mt * 16 + grp;
        int row1 = row0 + 8;
#pragma unroll
        for (int nt = 0; nt < 4; nt++) {
            int col = warp_n * 32 + nt * 8 + 2 * tig;
            float v0 = c[mt][nt][0], v1 = c[mt][nt][1];
            float v2 = c[mt][nt][2], v3 = c[mt][nt][3];
            v0 = (v0 > 0.f) ? v0 : 0.2f * v0;
            v1 = (v1 > 0.f) ? v1 : 0.2f * v1;
            v2 = (v2 > 0.f) ? v2 : 0.2f * v2;
            v3 = (v3 > 0.f) ? v3 : 0.2f * v3;
            if (row0 < M) *(float2*)(L + (size_t)row0 * 128 + col) = make_float2(v0, v1);
            if (row1 < M) *(float2*)(L + (size_t)row1 * 128 + col) = make_float2(v2, v3);
        }
    }
}

// ---------------- half write helper: 4 floats -> 4 halves at lane slot ----------------
__device__ __forceinline__ void store_h4(__half* base, size_t row, int lane, float4 v) {
    __half2 h0 = __floats2half2_rn(v.x, v.y);
    __half2 h1 = __floats2half2_rn(v.z, v.w);
    uint2 r;
    r.x = *reinterpret_cast<uint32_t*>(&h0);
    r.y = *reinterpret_cast<uint32_t*>(&h1);
    *((uint2*)(base + row * DIM) + lane) = r;
}

// ---------------- combine two lrelu buffers with softmax weights + l2norm (+fp16 out) ----------
__global__ void combine_l2norm_kernel(const float* __restrict__ La, const float* __restrict__ Lb,
                                      const float* __restrict__ mw, __half* __restrict__ outh,
                                      int nrows)
{
    int wid = (blockIdx.x * blockDim.x + threadIdx.x) >> 5;
    int lane = threadIdx.x & 31;
    if (wid >= nrows) return;
    float m0 = mw[0], m1 = mw[1];
    float mx = fmaxf(m0, m1);
    float e0 = __expf(m0 - mx), e1 = __expf(m1 - mx);
    float w0 = e0 / (e0 + e1), w1 = e1 / (e0 + e1);
    size_t off = (size_t)wid * DIM + lane * 4;
    float4 a = *(const float4*)(La + off);
    float4 b = *(const float4*)(Lb + off);
    float4 v;
    v.x = w0 * a.x + w1 * b.x;
    v.y = w0 * a.y + w1 * b.y;
    v.z = w0 * a.z + w1 * b.z;
    v.w = w0 * a.w + w1 * b.w;
    float s = v.x * v.x + v.y * v.y + v.z * v.z + v.w * v.w;
#pragma unroll
    for (int o = 16; o > 0; o >>= 1) s += __shfl_xor_sync(0xffffffffu, s, o);
    float inv = 1.f / fmaxf(sqrtf(s), 1e-12f);
    v.x *= inv; v.y *= inv; v.z *= inv; v.w *= inv;
    store_h4(outh, wid, lane, v);
}

// ---------------- fp16-gather CSR SpMM (warp per row) ----------------
__device__ __forceinline__ float4 gfetch_h(int col, int lane,
                                           const __half* __restrict__ xU,
                                           const __half* __restrict__ xI) {
    const __half* x = (col < USERS) ? (xU + (size_t)col * DIM)
                                    : (xI + (size_t)(col - USERS) * DIM);
    uint2 raw = __ldg((const uint2*)x + lane);
    __half2 h0 = *reinterpret_cast<__half2*>(&raw.x);
    __half2 h1 = *reinterpret_cast<__half2*>(&raw.y);
    float2 f0 = __half22float2(h0), f1 = __half22float2(h1);
    return make_float4(f0.x, f0.y, f1.x, f1.y);
}

// single spmm: fp32 out, optional fp16 out
__global__ void spmm_h_kernel(const int* __restrict__ rowptr, const float2* __restrict__ cv,
                              const __half* __restrict__ xU, const __half* __restrict__ xI,
                              float* __restrict__ out, __half* __restrict__ outh)
{
    int row = blockIdx.x * 8 + (threadIdx.x >> 5);
    int lane = threadIdx.x & 31;
    if (row >= NTOT) return;
    int s = rowptr[row], e = rowptr[row + 1];
    float4 acc = make_float4(0.f, 0.f, 0.f, 0.f);
    int i = s;
    for (; i + 2 <= e; i += 2) {
        float2 c0 = cv[i], c1 = cv[i + 1];
        float4 x0 = gfetch_h(__float_as_int(c0.x), lane, xU, xI);
        float4 x1 = gfetch_h(__float_as_int(c1.x), lane, xU, xI);
        acc.x += c0.y * x0.x + c1.y * x1.x;
        acc.y += c0.y * x0.y + c1.y * x1.y;
        acc.z += c0.y * x0.z + c1.y * x1.z;
        acc.w += c0.y * x0.w + c1.y * x1.w;
    }
    if (i < e) {
        float2 c0 = cv[i];
        float4 x0 = gfetch_h(__float_as_int(c0.x), lane, xU, xI);
        acc.x += c0.y * x0.x; acc.y += c0.y * x0.y;
        acc.z += c0.y * x0.z; acc.w += c0.y * x0.w;
    }
    *((float4*)(out + (size_t)row * DIM) + lane) = acc;
    if (outh) store_h4(outh, row, lane, acc);
}

// Dual SpMM, shared USER table: outA uses (xU, xIa), outB uses (xU, xIb); fp32+fp16 outs.
__global__ void spmm_h_dualU_kernel(const int* __restrict__ rowptr, const float2* __restrict__ cv,
                                    const __half* __restrict__ xU,
                                    const __half* __restrict__ xIa, const __half* __restrict__ xIb,
                                    float* __restrict__ outA, float* __restrict__ outB,
                                    __half* __restrict__ outAh, __half* __restrict__ outBh)
{
    int row = blockIdx.x * 8 + (threadIdx.x >> 5);
    int lane = threadIdx.x & 31;
    if (row >= NTOT) return;
    int s = rowptr[row], e = rowptr[row + 1];
    float4 accA = make_float4(0.f, 0.f, 0.f, 0.f);
    float4 accB = make_float4(0.f, 0.f, 0.f, 0.f);
    for (int i = s; i < e; i++) {
        float2 c = cv[i];
        int col = __float_as_int(c.x);
        float4 xa, xb;
        if (col < USERS) {
            xa = gfetch_h(col, lane, xU, xU);
            xb = xa;
        } else {
            xa = gfetch_h(col, lane, xU, xIa);
            xb = gfetch_h(col, lane, xU, xIb);
        }
        accA.x += c.y * xa.x; accA.y += c.y * xa.y; accA.z += c.y * xa.z; accA.w += c.y * xa.w;
        accB.x += c.y * xb.x; accB.y += c.y * xb.y; accB.z += c.y * xb.z; accB.w += c.y * xb.w;
    }
    *((float4*)(outA + (size_t)row * DIM) + lane) = accA;
    *((float4*)(outB + (size_t)row * DIM) + lane) = accB;
    store_h4(outAh, row, lane, accA);
    store_h4(outBh, row, lane, accB);
}

// Dual SpMM, shared ITEM table: outA uses (xUa, xI), outB uses (xUb, xI).
__global__ void spmm_h_dualI_kernel(const int* __restrict__ rowptr, const float2* __restrict__ cv,
                                    const __half* __restrict__ xUa, const __half* __restrict__ xUb,
                                    const __half* __restrict__ xI,
                                    float* __restrict__ outA, float* __restrict__ outB)
{
    int row = blockIdx.x * 8 + (threadIdx.x >> 5);
    int lane = threadIdx.x & 31;
    if (row >= NTOT) return;
    int s = rowptr[row], e = rowptr[row + 1];
    float4 accA = make_float4(0.f, 0.f, 0.f, 0.f);
    float4 accB = make_float4(0.f, 0.f, 0.f, 0.f);
    for (int i = s; i < e; i++) {
        float2 c = cv[i];
        int col = __float_as_int(c.x);
        float4 xa, xb;
        if (col < USERS) {
            xa = gfetch_h(col, lane, xUa, xUa);
            xb = gfetch_h(col, lane, xUb, xUb);
        } else {
            xa = gfetch_h(col, lane, xUa, xI);
            xb = xa;
        }
        accA.x += c.y * xa.x; accA.y += c.y * xa.y; accA.z += c.y * xa.z; accA.w += c.y * xa.w;
        accB.x += c.y * xb.x; accB.y += c.y * xb.y; accB.z += c.y * xb.z; accB.w += c.y * xb.w;
    }
    *((float4*)(outA + (size_t)row * DIM) + lane) = accA;
    *((float4*)(outB + (size_t)row * DIM) + lane) = accB;
}

// ---------------- combine into modal (fp32 + fp16) ----------------
__global__ void combine_kernel(const float4* __restrict__ id, const float4* __restrict__ id2,
                               const float4* __restrict__ idadj,
                               const float4* __restrict__ ft, const float4* __restrict__ ft2,
                               const float4* __restrict__ ftadj,
                               float4* __restrict__ modal, __half* __restrict__ modalh, int n4)
{
    int i = blockIdx.x * blockDim.x + threadIdx.x;
    if (i >= n4) return;
    float4 a = id[i], b = id2[i], c = idadj[i];
    float4 d = ft[i], e = ft2[i], f = ftadj[i];
    float4 m;
    m.x = 0.5f * (a.x + b.x + 0.2f * c.x) + 0.5f * (d.x + e.x + 0.2f * f.x);
    m.y = 0.5f * (a.y + b.y + 0.2f * c.y) + 0.5f * (d.y + e.y + 0.2f * f.y);
    m.z = 0.5f * (a.z + b.z + 0.2f * c.z) + 0.5f * (d.z + e.z + 0.2f * f.z);
    m.w = 0.5f * (a.w + b.w + 0.2f * c.w) + 0.5f * (d.w + e.w + 0.2f * f.w);
    modal[i] = m;
    __half2 h0 = __floats2half2_rn(m.x, m.y);
    __half2 h1 = __floats2half2_rn(m.z, m.w);
    uint2 r;
    r.x = *reinterpret_cast<uint32_t*>(&h0);
    r.y = *reinterpret_cast<uint32_t*>(&h1);
    ((uint2*)modalh)[i] = r;
}

// ---------------- final: out = modal + A + B + 0.5 * l2norm(modal) ----------------
__global__ void final_kernel(const float* __restrict__ modal, const float* __restrict__ A,
                             const float* __restrict__ B, float* __restrict__ out, int nrows)
{
    int wid = (blockIdx.x * blockDim.x + threadIdx.x) >> 5;
    int lane = threadIdx.x & 31;
    if (wid >= nrows) return;
    size_t off = (size_t)wid * DIM + lane * 4;
    float4 m = *(const float4*)(modal + off);
    float4 a = *(const float4*)(A + off);
    float4 b = *(const float4*)(B + off);
    float s = m.x * m.x + m.y * m.y + m.z * m.z + m.w * m.w;
#pragma unroll
    for (int o = 16; o > 0; o >>= 1) s += __shfl_xor_sync(0xffffffffu, s, o);
    float inv = 0.5f / fmaxf(sqrtf(s), 1e-12f);   // RIS_LAMBDA / norm
    float4 r;
    r.x = m.x + a.x + b.x + inv * m.x;
    r.y = m.y + a.y + b.y + inv * m.y;
    r.z = m.z + a.z + b.z + inv * m.z;
    r.w = m.w + a.w + b.w + inv * m.w;
    *(float4*)(out + off) = r;
}

// ---------------- host ----------------
extern "C" void kernel_launch(void* const* d_in, const int* in_sizes, int n_in,
                              void* d_out, int out_size)
{
    const int*   adj_rows = (const int*)d_in[0];
    const int*   adj_cols = (const int*)d_in[1];
    const float* adj_vals = (const float*)d_in[2];
    const int*   id_rows  = (const int*)d_in[3];
    const int*   id_cols  = (const int*)d_in[4];
    const float* id_vals  = (const float*)d_in[5];
    const int*   ft_rows  = (const int*)d_in[6];
    const int*   ft_cols  = (const int*)d_in[7];
    const float* ft_vals  = (const float*)d_in[8];
    const float* uEmb     = (const float*)d_in[9];
    const float* iEmb     = (const float*)d_in[10];
    const float* img_emb  = (const float*)d_in[11];
    const float* img_id   = (const float*)d_in[12];
    const float* txt_emb  = (const float*)d_in[13];
    const float* txt_id   = (const float*)d_in[14];
    const float* img_tr   = (const float*)d_in[15];
    const float* img_id_tr= (const float*)d_in[16];
    const float* txt_tr   = (const float*)d_in[17];
    const float* txt_id_tr= (const float*)d_in[18];
    const float* mw       = (const float*)d_in[19];
    float* out = (float*)d_out;

    int E_adj = in_sizes[0];
    int E_id  = in_sizes[3];
    int E_ft  = in_sizes[6];
    int E_tot = E_adj + E_id + E_ft;

    float *pId, *pId2, *pIdAdj, *pFt, *pFt2, *pFtAdj, *pModal, *pA, *pB;
    __half *hU, *hI, *hAllID, *hAllFt, *hId, *hFt, *hModal, *hA;
    float2 *cvAll;
    int *pRp, *pCounts, *pOffs, *pBsums;
    cudaGetSymbolAddress((void**)&pId,     g_Id);
    cudaGetSymbolAddress((void**)&pId2,    g_Id2);
    cudaGetSymbolAddress((void**)&pIdAdj,  g_IdAdj);
    cudaGetSymbolAddress((void**)&pFt,     g_Ft);
    cudaGetSymbolAddress((void**)&pFt2,    g_Ft2);
    cudaGetSymbolAddress((void**)&pFtAdj,  g_FtAdj);
    cudaGetSymbolAddress((void**)&pModal,  g_modal);
    cudaGetSymbolAddress((void**)&pA,      g_tmpA);
    cudaGetSymbolAddress((void**)&pB,      g_tmpB);
    cudaGetSymbolAddress((void**)&hU,      g_h_u);
    cudaGetSymbolAddress((void**)&hI,      g_h_i);
    cudaGetSymbolAddress((void**)&hAllID,  g_h_allID);
    cudaGetSymbolAddress((void**)&hAllFt,  g_h_allFt);
    cudaGetSymbolAddress((void**)&hId,     g_h_Id);
    cudaGetSymbolAddress((void**)&hFt,     g_h_Ft);
    cudaGetSymbolAddress((void**)&hModal,  g_h_modal);
    cudaGetSymbolAddress((void**)&hA,      g_h_A);
    cudaGetSymbolAddress((void**)&cvAll,   g_cv_all);
    cudaGetSymbolAddress((void**)&pRp,     g_rp);
    cudaGetSymbolAddress((void**)&pCounts, g_counts);
    cudaGetSymbolAddress((void**)&pOffs,   g_offs);
    cudaGetSymbolAddress((void**)&pBsums,  g_bsums);

    // GEMM lrelu buffers live in g_tmpA/g_tmpB (free until GNN layers)
    float* L_imgid = pA;
    float* L_txtid = pA + (size_t)ITEMS * DIM;
    float* L_img   = pB;
    float* L_txt   = pB + (size_t)ITEMS * DIM;

    // 1) batched CSR build for all three sparse matrices
    {
        int n = 3 * NSEG;
        int nb = (n + SCAN_BLOCK - 1) / SCAN_BLOCK;
        zero_int_kernel<<<(n + 255) / 256, 256>>>(pCounts, n);
        hist3_kernel<<<(E_tot + 255) / 256, 256>>>(adj_rows, id_rows, ft_rows,
                                                   E_adj, E_id, E_ft, pCounts);
        scan1_kernel<<<nb, SCAN_BLOCK>>>(pCounts, pRp, pBsums, n);
        scan2_kernel<<<1, NB_MAX>>>(pBsums, nb);
        scan3_kernel<<<nb, SCAN_BLOCK>>>(pRp, pBsums, pOffs, n);
        scatter3_kernel<<<(E_tot + 255) / 256, 256>>>(adj_rows, adj_cols, adj_vals,
                                                      id_rows, id_cols, id_vals,
                                                      ft_rows, ft_cols, ft_vals,
                                                      E_adj, E_id, E_ft, pOffs, cvAll);
    }
    const int* rpAdj = pRp;
    const int* rpId  = pRp + NSEG;
    const int* rpFt  = pRp + 2 * NSEG;

    // 2) fp16 copies of input embeddings
    {
        int n4u = USERS * DIM / 4, n4i = ITEMS * DIM / 4;
        f2h_kernel<<<(n4u + 255) / 256, 256>>>((const float4*)uEmb, (uint2*)hU, n4u);
        f2h_kernel<<<(n4i + 255) / 256, 256>>>((const float4*)iEmb, (uint2*)hI, n4i);
    }

    // 3) all four modality GEMMs in one launch (tf32 tensor cores)
    dim3 ggrid((ITEMS + 127) / 128, 4);
    gemm4_kernel<<<ggrid, 256>>>(img_id, txt_id, img_emb, txt_emb,
                                 img_id_tr, txt_id_tr, img_tr, txt_tr,
                                 L_imgid, L_txtid, L_img, L_txt);

    // 4) weighted combine + l2norm -> fp16 gather tables
    int l2_blocks = (ITEMS * 32 + 255) / 256;
    combine_l2norm_kernel<<<l2_blocks, 256>>>(L_imgid, L_txtid, mw, hAllID, ITEMS);
    combine_l2norm_kernel<<<l2_blocks, 256>>>(L_img,   L_txt,   mw, hAllFt, ITEMS);

    // 5) SpMMs (fp16 gather, fp32 accumulate)
    int spmm_blocks = (NTOT + 7) / 8;
    spmm_h_kernel<<<spmm_blocks, 256>>>(rpId, cvAll, hU, hI, pIdAdj, nullptr);
    spmm_h_kernel<<<spmm_blocks, 256>>>(rpFt, cvAll, hU, hI, pFtAdj, nullptr);
    spmm_h_dualU_kernel<<<spmm_blocks, 256>>>(rpAdj, cvAll, hU, hAllID, hAllFt,
                                              pId, pFt, hId, hFt);
    spmm_h_dualI_kernel<<<spmm_blocks, 256>>>(rpAdj, cvAll, hId, hFt, hI, pId2, pFt2);

    // 6) combine into modal (fp32 + fp16)
    int n4 = (int)(((size_t)NTOT * DIM) / 4);
    combine_kernel<<<(n4 + 255) / 256, 256>>>((float4*)pId, (float4*)pId2, (float4*)pIdAdj,
                                              (float4*)pFt, (float4*)pFt2, (float4*)pFtAdj,
                                              (float4*)pModal, hModal, n4);

    // 7) 2-layer GNN propagation (overwrites g_tmpA/g_tmpB; GEMM buffers already consumed)
    spmm_h_kernel<<<spmm_blocks, 256>>>(rpAdj, cvAll, hModal, hModal + (size_t)USERS * DIM, pA, hA);
    spmm_h_kernel<<<spmm_blocks, 256>>>(rpAdj, cvAll, hA, hA + (size_t)USERS * DIM, pB, nullptr);

    // 8) final: out = modal + A + B + 0.5 * l2norm(modal)
    int fin_blocks = (NTOT * 32 + 255) / 256;
    final_kernel<<<fin_blocks, 256>>>(pModal, pA, pB, out, NTOT);

    (void)n_in; (void)out_size;
}

// round 6
// speedup vs baseline: 3.9144x; 1.1144x over previous
#include <cuda_runtime.h>
#include <cuda_fp16.h>
#include <cstdint>
#include <cstddef>

#define USERS 50000
#define ITEMS 50000
#define NTOT  100000
#define DIM   128
#define EMAX  1700000
#define SCAN_BLOCK 1024
#define NB_MAX 512
#define NSEG  (NTOT + 1)

// ---------------- scratch (device globals; allocation-free) ----------------
__device__ float g_Id    [(size_t)NTOT * DIM];
__device__ float g_Id2   [(size_t)NTOT * DIM];
__device__ float g_IdAdj [(size_t)NTOT * DIM];
__device__ float g_Ft    [(size_t)NTOT * DIM];
__device__ float g_Ft2   [(size_t)NTOT * DIM];
__device__ float g_FtAdj [(size_t)NTOT * DIM];
__device__ float g_modal [(size_t)NTOT * DIM];
__device__ float g_tmpA  [(size_t)NTOT * DIM];   // also hosts GEMM L0/L1
__device__ float g_tmpB  [(size_t)NTOT * DIM];   // also hosts GEMM L2/L3

// fp16 gather tables
__device__ __half g_h_u     [(size_t)USERS * DIM];
__device__ __half g_h_i     [(size_t)ITEMS * DIM];
__device__ __half g_h_allID [(size_t)ITEMS * DIM];
__device__ __half g_h_allFt [(size_t)ITEMS * DIM];
__device__ __half g_h_Id    [(size_t)NTOT * DIM];
__device__ __half g_h_Ft    [(size_t)NTOT * DIM];
__device__ __half g_h_modal [(size_t)NTOT * DIM];
__device__ __half g_h_A     [(size_t)NTOT * DIM];

// batched CSR for 3 matrices (concatenated)
__device__ float2 g_cv_all [3 * EMAX];
__device__ int    g_rp     [3 * NSEG];
__device__ int    g_counts [3 * NSEG];
__device__ int    g_offs   [3 * NSEG];
__device__ int    g_bsums  [NB_MAX];

// ---------------- small utility kernels ----------------
__global__ void zero_int_kernel(int* __restrict__ p, int n) {
    int i = blockIdx.x * blockDim.x + threadIdx.x;
    if (i < n) p[i] = 0;
}

__global__ void f2h_kernel(const float4* __restrict__ in, uint2* __restrict__ outh, int n4) {
    int i = blockIdx.x * blockDim.x + threadIdx.x;
    if (i >= n4) return;
    float4 v = in[i];
    __half2 h0 = __floats2half2_rn(v.x, v.y);
    __half2 h1 = __floats2half2_rn(v.z, v.w);
    uint2 r;
    r.x = *reinterpret_cast<uint32_t*>(&h0);
    r.y = *reinterpret_cast<uint32_t*>(&h1);
    outh[i] = r;
}

// ---------------- batched counting sort: hist / scan / scatter ----------------
__global__ void hist3_kernel(const int* __restrict__ r0, const int* __restrict__ r1,
                             const int* __restrict__ r2, int n0, int n1, int n2,
                             int* __restrict__ counts) {
    int i = blockIdx.x * blockDim.x + threadIdx.x;
    int nt = n0 + n1 + n2;
    if (i >= nt) return;
    int row, seg;
    if (i < n0)            { seg = 0; row = r0[i]; }
    else if (i < n0 + n1)  { seg = 1; row = r1[i - n0]; }
    else                   { seg = 2; row = r2[i - n0 - n1]; }
    atomicAdd(&counts[seg * NSEG + row], 1);
}

__global__ void scan1_kernel(const int* __restrict__ counts, int* __restrict__ rowptr,
                             int* __restrict__ bsums, int n) {
    __shared__ int sh[SCAN_BLOCK];
    int g = blockIdx.x * SCAN_BLOCK + threadIdx.x;
    int v = (g < n) ? counts[g] : 0;
    sh[threadIdx.x] = v;
    __syncthreads();
    for (int off = 1; off < SCAN_BLOCK; off <<= 1) {
        int t = (threadIdx.x >= off) ? sh[threadIdx.x - off] : 0;
        __syncthreads();
        sh[threadIdx.x] += t;
        __syncthreads();
    }
    if (g < n) rowptr[g] = sh[threadIdx.x] - v;   // exclusive
    if (threadIdx.x == SCAN_BLOCK - 1) bsums[blockIdx.x] = sh[threadIdx.x];
}

__global__ void scan2_kernel(int* __restrict__ bsums, int nb) {
    __shared__ int sh[NB_MAX];
    int v = (threadIdx.x < nb) ? bsums[threadIdx.x] : 0;
    sh[threadIdx.x] = v;
    __syncthreads();
    for (int off = 1; off < NB_MAX; off <<= 1) {
        int t = (threadIdx.x >= off) ? sh[threadIdx.x - off] : 0;
        __syncthreads();
        sh[threadIdx.x] += t;
        __syncthreads();
    }
    if (threadIdx.x < nb) bsums[threadIdx.x] = sh[threadIdx.x] - v;  // exclusive
}

__global__ void scan3_kernel(int* __restrict__ rowptr, const int* __restrict__ bsums,
                             int* __restrict__ offs, int n) {
    int g = blockIdx.x * SCAN_BLOCK + threadIdx.x;
    if (g < n) {
        int v = rowptr[g] + bsums[blockIdx.x];
        rowptr[g] = v;
        offs[g] = v;
    }
}

__global__ void scatter3_kernel(const int* __restrict__ r0, const int* __restrict__ c0, const float* __restrict__ v0,
                                const int* __restrict__ r1, const int* __restrict__ c1, const float* __restrict__ v1,
                                const int* __restrict__ r2, const int* __restrict__ c2, const float* __restrict__ v2,
                                int n0, int n1, int n2,
                                int* __restrict__ offs, float2* __restrict__ cv) {
    int i = blockIdx.x * blockDim.x + threadIdx.x;
    int nt = n0 + n1 + n2;
    if (i >= nt) return;
    int row, seg, col; float val;
    if (i < n0)           { seg = 0; int j = i;            row = r0[j]; col = c0[j]; val = v0[j]; }
    else if (i < n0 + n1) { seg = 1; int j = i - n0;       row = r1[j]; col = c1[j]; val = v1[j]; }
    else                  { seg = 2; int j = i - n0 - n1;  row = r2[j]; col = c2[j]; val = v2[j]; }
    int pos = atomicAdd(&offs[seg * NSEG + row], 1);
    cv[pos] = make_float2(__int_as_float(col), val);
}

// ---------------- tf32 tensor-core GEMM with cp.async double buffering ----------------
__device__ __forceinline__ void mma_tf32(float c[4], uint32_t a0, uint32_t a1,
                                         uint32_t a2, uint32_t a3,
                                         uint32_t b0, uint32_t b1) {
    asm volatile(
        "mma.sync.aligned.m16n8k8.row.col.f32.tf32.tf32.f32 "
        "{%0,%1,%2,%3}, {%4,%5,%6,%7}, {%8,%9}, {%0,%1,%2,%3};"
        : "+f"(c[0]), "+f"(c[1]), "+f"(c[2]), "+f"(c[3])
        : "r"(a0), "r"(a1), "r"(a2), "r"(a3), "r"(b0), "r"(b1));
}

__device__ __forceinline__ void cp_async16(uint32_t smem_addr, const void* gsrc, int src_bytes) {
    asm volatile("cp.async.cg.shared.global [%0], [%1], 16, %2;"
                 :: "r"(smem_addr), "l"(gsrc), "r"(src_bytes));
}
__device__ __forceinline__ void cp_commit() {
    asm volatile("cp.async.commit_group;");
}
template <int N>
__device__ __forceinline__ void cp_wait() {
    asm volatile("cp.async.wait_group %0;" :: "n"(N));
}

#define AS_STRIDE 36
#define BS_STRIDE 132
#define AS_WORDS (128 * AS_STRIDE)     // 4608
#define BS_WORDS (32 * BS_STRIDE)      // 4224
#define GEMM_SMEM_WORDS (2 * (AS_WORDS + BS_WORDS))
#define GEMM_SMEM_BYTES (GEMM_SMEM_WORDS * 4)

// 4 GEMMs in one grid: blockIdx.y = gemm id. Raw fp32 bits fed to tf32 MMA (HW truncation).
__global__ __launch_bounds__(256, 2) void gemm4_kernel(
    const float* __restrict__ A0, const float* __restrict__ A1,
    const float* __restrict__ A2, const float* __restrict__ A3,
    const float* __restrict__ B0, const float* __restrict__ B1,
    const float* __restrict__ B2, const float* __restrict__ B3,
    float* __restrict__ L0, float* __restrict__ L1,
    float* __restrict__ L2, float* __restrict__ L3)
{
    extern __shared__ uint32_t smem[];
    uint32_t* As[2] = { smem, smem + AS_WORDS };
    uint32_t* Bs[2] = { smem + 2 * AS_WORDS, smem + 2 * AS_WORDS + BS_WORDS };

    int g = blockIdx.y;
    const float* A = (g == 0) ? A0 : (g == 1) ? A1 : (g == 2) ? A2 : A3;
    const float* B = (g == 0) ? B0 : (g == 1) ? B1 : (g == 2) ? B2 : B3;
    float*       L = (g == 0) ? L0 : (g == 1) ? L1 : (g == 2) ? L2 : L3;
    int K = (g & 1) ? 768 : 1024;
    const int M = ITEMS;
    int nIter = K >> 5;

    int tid = threadIdx.x;
    int wid = tid >> 5;
    int lane = tid & 31;
    int grp = lane >> 2;
    int tig = lane & 3;
    int warp_m = wid & 1;
    int warp_n = wid >> 1;
    int blockRow = blockIdx.x * 128;

    // per-thread copy coordinates (4 chunks of 16B each for A and B)
    int a_row[4], a_kq[4], b_row[4], b_nq[4];
#pragma unroll
    for (int t = 0; t < 4; t++) {
        int idx = tid + t * 256;
        a_row[t] = idx >> 3;  a_kq[t] = (idx & 7) << 2;
        b_row[t] = idx >> 5;  b_nq[t] = (idx & 31) << 2;
    }

    auto load_stage = [&](int it, int buf) {
        int k0 = it << 5;
#pragma unroll
        for (int t = 0; t < 4; t++) {
            int gm = blockRow + a_row[t];
            uint32_t dst = (uint32_t)__cvta_generic_to_shared(&As[buf][a_row[t] * AS_STRIDE + a_kq[t]]);
            const float* src = A + (size_t)gm * K + k0 + a_kq[t];
            cp_async16(dst, src, (gm < M) ? 16 : 0);
        }
#pragma unroll
        for (int t = 0; t < 4; t++) {
            uint32_t dst = (uint32_t)__cvta_generic_to_shared(&Bs[buf][b_row[t] * BS_STRIDE + b_nq[t]]);
            const float* src = B + (size_t)(k0 + b_row[t]) * 128 + b_nq[t];
            cp_async16(dst, src, 16);
        }
        cp_commit();
    };

    float c[4][4][4];
#pragma unroll
    for (int mt = 0; mt < 4; mt++)
#pragma unroll
        for (int nt = 0; nt < 4; nt++)
#pragma unroll
            for (int f = 0; f < 4; f++) c[mt][nt][f] = 0.f;

    load_stage(0, 0);

    for (int it = 0; it < nIter; it++) {
        int cur = it & 1;
        if (it + 1 < nIter) {
            load_stage(it + 1, cur ^ 1);
            cp_wait<1>();
        } else {
            cp_wait<0>();
        }
        __syncthreads();

        uint32_t* as = As[cur];
        uint32_t* bs = Bs[cur];
#pragma unroll
        for (int ks = 0; ks < 4; ks++) {
            int kb = ks * 8;
            uint32_t a[4][4];
#pragma unroll
            for (int mt = 0; mt < 4; mt++) {
                int mb = warp_m * 64 + mt * 16;
                a[mt][0] = as[(mb + grp)     * AS_STRIDE + kb + tig];
                a[mt][1] = as[(mb + grp + 8) * AS_STRIDE + kb + tig];
                a[mt][2] = as[(mb + grp)     * AS_STRIDE + kb + tig + 4];
                a[mt][3] = as[(mb + grp + 8) * AS_STRIDE + kb + tig + 4];
            }
            uint32_t b[4][2];
#pragma unroll
            for (int nt = 0; nt < 4; nt++) {
                int nb = warp_n * 32 + nt * 8;
                b[nt][0] = bs[(kb + tig)     * BS_STRIDE + nb + grp];
                b[nt][1] = bs[(kb + tig + 4) * BS_STRIDE + nb + grp];
            }
#pragma unroll
            for (int mt = 0; mt < 4; mt++)
#pragma unroll
                for (int nt = 0; nt < 4; nt++)
                    mma_tf32(c[mt][nt], a[mt][0], a[mt][1], a[mt][2], a[mt][3],
                             b[nt][0], b[nt][1]);
        }
        __syncthreads();
    }

    // epilogue: leaky_relu(0.2), store
#pragma unroll
    for (int mt = 0; mt < 4; mt++) {
        int row0 = blockRow + warp_m * 64 + mt * 16 + grp;
        int row1 = row0 + 8;
#pragma unroll
        for (int nt = 0; nt < 4; nt++) {
            int col = warp_n * 32 + nt * 8 + 2 * tig;
            float v0 = c[mt][nt][0], v1 = c[mt][nt][1];
            float v2 = c[mt][nt][2], v3 = c[mt][nt][3];
            v0 = (v0 > 0.f) ? v0 : 0.2f * v0;
            v1 = (v1 > 0.f) ? v1 : 0.2f * v1;
            v2 = (v2 > 0.f) ? v2 : 0.2f * v2;
            v3 = (v3 > 0.f) ? v3 : 0.2f * v3;
            if (row0 < M) *(float2*)(L + (size_t)row0 * 128 + col) = make_float2(v0, v1);
            if (row1 < M) *(float2*)(L + (size_t)row1 * 128 + col) = make_float2(v2, v3);
        }
    }
}

// ---------------- half write helper ----------------
__device__ __forceinline__ void store_h4(__half* base, size_t row, int lane, float4 v) {
    __half2 h0 = __floats2half2_rn(v.x, v.y);
    __half2 h1 = __floats2half2_rn(v.z, v.w);
    uint2 r;
    r.x = *reinterpret_cast<uint32_t*>(&h0);
    r.y = *reinterpret_cast<uint32_t*>(&h1);
    *((uint2*)(base + row * DIM) + lane) = r;
}

// ---------------- combine two lrelu buffers with softmax weights + l2norm (fp16 out) --------
__global__ void combine_l2norm_kernel(const float* __restrict__ La, const float* __restrict__ Lb,
                                      const float* __restrict__ mw, __half* __restrict__ outh,
                                      int nrows)
{
    int wid = (blockIdx.x * blockDim.x + threadIdx.x) >> 5;
    int lane = threadIdx.x & 31;
    if (wid >= nrows) return;
    float m0 = mw[0], m1 = mw[1];
    float mx = fmaxf(m0, m1);
    float e0 = __expf(m0 - mx), e1 = __expf(m1 - mx);
    float w0 = e0 / (e0 + e1), w1 = e1 / (e0 + e1);
    size_t off = (size_t)wid * DIM + lane * 4;
    float4 a = *(const float4*)(La + off);
    float4 b = *(const float4*)(Lb + off);
    float4 v;
    v.x = w0 * a.x + w1 * b.x;
    v.y = w0 * a.y + w1 * b.y;
    v.z = w0 * a.z + w1 * b.z;
    v.w = w0 * a.w + w1 * b.w;
    float s = v.x * v.x + v.y * v.y + v.z * v.z + v.w * v.w;
#pragma unroll
    for (int o = 16; o > 0; o >>= 1) s += __shfl_xor_sync(0xffffffffu, s, o);
    float inv = 1.f / fmaxf(sqrtf(s), 1e-12f);
    v.x *= inv; v.y *= inv; v.z *= inv; v.w *= inv;
    store_h4(outh, wid, lane, v);
}

// ---------------- fp16-gather CSR SpMM (warp per row) ----------------
__device__ __forceinline__ float4 gfetch_h(int col, int lane,
                                           const __half* __restrict__ xU,
                                           const __half* __restrict__ xI) {
    const __half* x = (col < USERS) ? (xU + (size_t)col * DIM)
                                    : (xI + (size_t)(col - USERS) * DIM);
    uint2 raw = __ldg((const uint2*)x + lane);
    __half2 h0 = *reinterpret_cast<__half2*>(&raw.x);
    __half2 h1 = *reinterpret_cast<__half2*>(&raw.y);
    float2 f0 = __half22float2(h0), f1 = __half22float2(h1);
    return make_float4(f0.x, f0.y, f1.x, f1.y);
}
__device__ __forceinline__ void facc(float4& a, float w, float4 x) {
    a.x += w * x.x; a.y += w * x.y; a.z += w * x.z; a.w += w * x.w;
}

__global__ void spmm_h_kernel(const int* __restrict__ rowptr, const float2* __restrict__ cv,
                              const __half* __restrict__ xU, const __half* __restrict__ xI,
                              float* __restrict__ out, __half* __restrict__ outh)
{
    int row = blockIdx.x * 8 + (threadIdx.x >> 5);
    int lane = threadIdx.x & 31;
    if (row >= NTOT) return;
    int s = rowptr[row], e = rowptr[row + 1];
    float4 acc = make_float4(0.f, 0.f, 0.f, 0.f);
    int i = s;
    for (; i + 4 <= e; i += 4) {
        float2 c0 = cv[i], c1 = cv[i + 1], c2 = cv[i + 2], c3 = cv[i + 3];
        float4 x0 = gfetch_h(__float_as_int(c0.x), lane, xU, xI);
        float4 x1 = gfetch_h(__float_as_int(c1.x), lane, xU, xI);
        float4 x2 = gfetch_h(__float_as_int(c2.x), lane, xU, xI);
        float4 x3 = gfetch_h(__float_as_int(c3.x), lane, xU, xI);
        facc(acc, c0.y, x0); facc(acc, c1.y, x1);
        facc(acc, c2.y, x2); facc(acc, c3.y, x3);
    }
    for (; i < e; i++) {
        float2 c0 = cv[i];
        float4 x0 = gfetch_h(__float_as_int(c0.x), lane, xU, xI);
        facc(acc, c0.y, x0);
    }
    *((float4*)(out + (size_t)row * DIM) + lane) = acc;
    if (outh) store_h4(outh, row, lane, acc);
}

// Dual SpMM, shared USER table: outA uses (xU, xIa), outB uses (xU, xIb); fp32+fp16 outs.
__global__ void spmm_h_dualU_kernel(const int* __restrict__ rowptr, const float2* __restrict__ cv,
                                    const __half* __restrict__ xU,
                                    const __half* __restrict__ xIa, const __half* __restrict__ xIb,
                                    float* __restrict__ outA, float* __restrict__ outB,
                                    __half* __restrict__ outAh, __half* __restrict__ outBh)
{
    int row = blockIdx.x * 8 + (threadIdx.x >> 5);
    int lane = threadIdx.x & 31;
    if (row >= NTOT) return;
    int s = rowptr[row], e = rowptr[row + 1];
    float4 accA = make_float4(0.f, 0.f, 0.f, 0.f);
    float4 accB = make_float4(0.f, 0.f, 0.f, 0.f);
    auto body = [&](float2 c) {
        int col = __float_as_int(c.x);
        float4 xa, xb;
        if (col < USERS) {
            xa = gfetch_h(col, lane, xU, xU);
            xb = xa;
        } else {
            xa = gfetch_h(col, lane, xU, xIa);
            xb = gfetch_h(col, lane, xU, xIb);
        }
        facc(accA, c.y, xa); facc(accB, c.y, xb);
    };
    int i = s;
    for (; i + 2 <= e; i += 2) {
        float2 c0 = cv[i], c1 = cv[i + 1];
        body(c0); body(c1);
    }
    if (i < e) body(cv[i]);
    *((float4*)(outA + (size_t)row * DIM) + lane) = accA;
    *((float4*)(outB + (size_t)row * DIM) + lane) = accB;
    store_h4(outAh, row, lane, accA);
    store_h4(outBh, row, lane, accB);
}

// Dual SpMM, shared ITEM table: outA uses (xUa, xI), outB uses (xUb, xI).
__global__ void spmm_h_dualI_kernel(const int* __restrict__ rowptr, const float2* __restrict__ cv,
                                    const __half* __restrict__ xUa, const __half* __restrict__ xUb,
                                    const __half* __restrict__ xI,
                                    float* __restrict__ outA, float* __restrict__ outB)
{
    int row = blockIdx.x * 8 + (threadIdx.x >> 5);
    int lane = threadIdx.x & 31;
    if (row >= NTOT) return;
    int s = rowptr[row], e = rowptr[row + 1];
    float4 accA = make_float4(0.f, 0.f, 0.f, 0.f);
    float4 accB = make_float4(0.f, 0.f, 0.f, 0.f);
    auto body = [&](float2 c) {
        int col = __float_as_int(c.x);
        float4 xa, xb;
        if (col < USERS) {
            xa = gfetch_h(col, lane, xUa, xUa);
            xb = gfetch_h(col, lane, xUb, xUb);
        } else {
            xa = gfetch_h(col, lane, xUa, xI);
            xb = xa;
        }
        facc(accA, c.y, xa); facc(accB, c.y, xb);
    };
    int i = s;
    for (; i + 2 <= e; i += 2) {
        float2 c0 = cv[i], c1 = cv[i + 1];
        body(c0); body(c1);
    }
    if (i < e) body(cv[i]);
    *((float4*)(outA + (size_t)row * DIM) + lane) = accA;
    *((float4*)(outB + (size_t)row * DIM) + lane) = accB;
}

// ---------------- combine into modal (fp32 + fp16) ----------------
__global__ void combine_kernel(const float4* __restrict__ id, const float4* __restrict__ id2,
                               const float4* __restrict__ idadj,
                               const float4* __restrict__ ft, const float4* __restrict__ ft2,
                               const float4* __restrict__ ftadj,
                               float4* __restrict__ modal, __half* __restrict__ modalh, int n4)
{
    int i = blockIdx.x * blockDim.x + threadIdx.x;
    if (i >= n4) return;
    float4 a = id[i], b = id2[i], c = idadj[i];
    float4 d = ft[i], e = ft2[i], f = ftadj[i];
    float4 m;
    m.x = 0.5f * (a.x + b.x + 0.2f * c.x) + 0.5f * (d.x + e.x + 0.2f * f.x);
    m.y = 0.5f * (a.y + b.y + 0.2f * c.y) + 0.5f * (d.y + e.y + 0.2f * f.y);
    m.z = 0.5f * (a.z + b.z + 0.2f * c.z) + 0.5f * (d.z + e.z + 0.2f * f.z);
    m.w = 0.5f * (a.w + b.w + 0.2f * c.w) + 0.5f * (d.w + e.w + 0.2f * f.w);
    modal[i] = m;
    __half2 h0 = __floats2half2_rn(m.x, m.y);
    __half2 h1 = __floats2half2_rn(m.z, m.w);
    uint2 r;
    r.x = *reinterpret_cast<uint32_t*>(&h0);
    r.y = *reinterpret_cast<uint32_t*>(&h1);
    ((uint2*)modalh)[i] = r;
}

// ---------------- final: out = modal + A + B + 0.5 * l2norm(modal) ----------------
__global__ void final_kernel(const float* __restrict__ modal, const float* __restrict__ A,
                             const float* __restrict__ B, float* __restrict__ out, int nrows)
{
    int wid = (blockIdx.x * blockDim.x + threadIdx.x) >> 5;
    int lane = threadIdx.x & 31;
    if (wid >= nrows) return;
    size_t off = (size_t)wid * DIM + lane * 4;
    float4 m = *(const float4*)(modal + off);
    float4 a = *(const float4*)(A + off);
    float4 b = *(const float4*)(B + off);
    float s = m.x * m.x + m.y * m.y + m.z * m.z + m.w * m.w;
#pragma unroll
    for (int o = 16; o > 0; o >>= 1) s += __shfl_xor_sync(0xffffffffu, s, o);
    float inv = 0.5f / fmaxf(sqrtf(s), 1e-12f);   // RIS_LAMBDA / norm
    float4 r;
    r.x = m.x + a.x + b.x + inv * m.x;
    r.y = m.y + a.y + b.y + inv * m.y;
    r.z = m.z + a.z + b.z + inv * m.z;
    r.w = m.w + a.w + b.w + inv * m.w;
    *(float4*)(out + off) = r;
}

// ---------------- host ----------------
extern "C" void kernel_launch(void* const* d_in, const int* in_sizes, int n_in,
                              void* d_out, int out_size)
{
    const int*   adj_rows = (const int*)d_in[0];
    const int*   adj_cols = (const int*)d_in[1];
    const float* adj_vals = (const float*)d_in[2];
    const int*   id_rows  = (const int*)d_in[3];
    const int*   id_cols  = (const int*)d_in[4];
    const float* id_vals  = (const float*)d_in[5];
    const int*   ft_rows  = (const int*)d_in[6];
    const int*   ft_cols  = (const int*)d_in[7];
    const float* ft_vals  = (const float*)d_in[8];
    const float* uEmb     = (const float*)d_in[9];
    const float* iEmb     = (const float*)d_in[10];
    const float* img_emb  = (const float*)d_in[11];
    const float* img_id   = (const float*)d_in[12];
    const float* txt_emb  = (const float*)d_in[13];
    const float* txt_id   = (const float*)d_in[14];
    const float* img_tr   = (const float*)d_in[15];
    const float* img_id_tr= (const float*)d_in[16];
    const float* txt_tr   = (const float*)d_in[17];
    const float* txt_id_tr= (const float*)d_in[18];
    const float* mw       = (const float*)d_in[19];
    float* out = (float*)d_out;

    int E_adj = in_sizes[0];
    int E_id  = in_sizes[3];
    int E_ft  = in_sizes[6];
    int E_tot = E_adj + E_id + E_ft;

    float *pId, *pId2, *pIdAdj, *pFt, *pFt2, *pFtAdj, *pModal, *pA, *pB;
    __half *hU, *hI, *hAllID, *hAllFt, *hId, *hFt, *hModal, *hA;
    float2 *cvAll;
    int *pRp, *pCounts, *pOffs, *pBsums;
    cudaGetSymbolAddress((void**)&pId,     g_Id);
    cudaGetSymbolAddress((void**)&pId2,    g_Id2);
    cudaGetSymbolAddress((void**)&pIdAdj,  g_IdAdj);
    cudaGetSymbolAddress((void**)&pFt,     g_Ft);
    cudaGetSymbolAddress((void**)&pFt2,    g_Ft2);
    cudaGetSymbolAddress((void**)&pFtAdj,  g_FtAdj);
    cudaGetSymbolAddress((void**)&pModal,  g_modal);
    cudaGetSymbolAddress((void**)&pA,      g_tmpA);
    cudaGetSymbolAddress((void**)&pB,      g_tmpB);
    cudaGetSymbolAddress((void**)&hU,      g_h_u);
    cudaGetSymbolAddress((void**)&hI,      g_h_i);
    cudaGetSymbolAddress((void**)&hAllID,  g_h_allID);
    cudaGetSymbolAddress((void**)&hAllFt,  g_h_allFt);
    cudaGetSymbolAddress((void**)&hId,     g_h_Id);
    cudaGetSymbolAddress((void**)&hFt,     g_h_Ft);
    cudaGetSymbolAddress((void**)&hModal,  g_h_modal);
    cudaGetSymbolAddress((void**)&hA,      g_h_A);
    cudaGetSymbolAddress((void**)&cvAll,   g_cv_all);
    cudaGetSymbolAddress((void**)&pRp,     g_rp);
    cudaGetSymbolAddress((void**)&pCounts, g_counts);
    cudaGetSymbolAddress((void**)&pOffs,   g_offs);
    cudaGetSymbolAddress((void**)&pBsums,  g_bsums);

    // GEMM lrelu buffers live in g_tmpA/g_tmpB (free until GNN layers)
    float* L_imgid = pA;
    float* L_txtid = pA + (size_t)ITEMS * DIM;
    float* L_img   = pB;
    float* L_txt   = pB + (size_t)ITEMS * DIM;

    // 1) batched CSR build for all three sparse matrices
    {
        int n = 3 * NSEG;
        int nb = (n + SCAN_BLOCK - 1) / SCAN_BLOCK;
        zero_int_kernel<<<(n + 255) / 256, 256>>>(pCounts, n);
        hist3_kernel<<<(E_tot + 255) / 256, 256>>>(adj_rows, id_rows, ft_rows,
                                                   E_adj, E_id, E_ft, pCounts);
        scan1_kernel<<<nb, SCAN_BLOCK>>>(pCounts, pRp, pBsums, n);
        scan2_kernel<<<1, NB_MAX>>>(pBsums, nb);
        scan3_kernel<<<nb, SCAN_BLOCK>>>(pRp, pBsums, pOffs, n);
        scatter3_kernel<<<(E_tot + 255) / 256, 256>>>(adj_rows, adj_cols, adj_vals,
                                                      id_rows, id_cols, id_vals,
                                                      ft_rows, ft_cols, ft_vals,
                                                      E_adj, E_id, E_ft, pOffs, cvAll);
    }
    const int* rpAdj = pRp;
    const int* rpId  = pRp + NSEG;
    const int* rpFt  = pRp + 2 * NSEG;

    // 2) fp16 copies of input embeddings
    {
        int n4u = USERS * DIM / 4, n4i = ITEMS * DIM / 4;
        f2h_kernel<<<(n4u + 255) / 256, 256>>>((const float4*)uEmb, (uint2*)hU, n4u);
        f2h_kernel<<<(n4i + 255) / 256, 256>>>((const float4*)iEmb, (uint2*)hI, n4i);
    }

    // 3) all four modality GEMMs in one launch (tf32 TC + cp.async double buffering)
    static bool smem_set = false;
    if (!smem_set) {
        cudaFuncSetAttribute(gemm4_kernel, cudaFuncAttributeMaxDynamicSharedMemorySize,
                             GEMM_SMEM_BYTES);
        smem_set = true;
    }
    dim3 ggrid((ITEMS + 127) / 128, 4);
    gemm4_kernel<<<ggrid, 256, GEMM_SMEM_BYTES>>>(img_id, txt_id, img_emb, txt_emb,
                                                  img_id_tr, txt_id_tr, img_tr, txt_tr,
                                                  L_imgid, L_txtid, L_img, L_txt);

    // 4) weighted combine + l2norm -> fp16 gather tables
    int l2_blocks = (ITEMS * 32 + 255) / 256;
    combine_l2norm_kernel<<<l2_blocks, 256>>>(L_imgid, L_txtid, mw, hAllID, ITEMS);
    combine_l2norm_kernel<<<l2_blocks, 256>>>(L_img,   L_txt,   mw, hAllFt, ITEMS);

    // 5) SpMMs (fp16 gather, fp32 accumulate)
    int spmm_blocks = (NTOT + 7) / 8;
    spmm_h_kernel<<<spmm_blocks, 256>>>(rpId, cvAll, hU, hI, pIdAdj, nullptr);
    spmm_h_kernel<<<spmm_blocks, 256>>>(rpFt, cvAll, hU, hI, pFtAdj, nullptr);
    spmm_h_dualU_kernel<<<spmm_blocks, 256>>>(rpAdj, cvAll, hU, hAllID, hAllFt,
                                              pId, pFt, hId, hFt);
    spmm_h_dualI_kernel<<<spmm_blocks, 256>>>(rpAdj, cvAll, hId, hFt, hI, pId2, pFt2);

    // 6) combine into modal (fp32 + fp16)
    int n4 = (int)(((size_t)NTOT * DIM) / 4);
    combine_kernel<<<(n4 + 255) / 256, 256>>>((float4*)pId, (float4*)pId2, (float4*)pIdAdj,
                                              (float4*)pFt, (float4*)pFt2, (float4*)pFtAdj,
                                              (float4*)pModal, hModal, n4);

    // 7) 2-layer GNN propagation (overwrites g_tmpA/g_tmpB; GEMM buffers already consumed)
    spmm_h_kernel<<<spmm_blocks, 256>>>(rpAdj, cvAll, hModal, hModal + (size_t)USERS * DIM, pA, hA);
    spmm_h_kernel<<<spmm_blocks, 256>>>(rpAdj, cvAll, hA, hA + (size_t)USERS * DIM, pB, nullptr);

    // 8) final: out = modal + A + B + 0.5 * l2norm(modal)
    int fin_blocks = (NTOT * 32 + 255) / 256;
    final_kernel<<<fin_blocks, 256>>>(pModal, pA, pB, out, NTOT);

    (void)n_in; (void)out_size;
}

// round 7
// speedup vs baseline: 3.9653x; 1.0130x over previous
#include <cuda_runtime.h>
#include <cuda_fp16.h>
#include <cstdint>
#include <cstddef>

#define USERS 50000
#define ITEMS 50000
#define NTOT  100000
#define DIM   128
#define EMAX  1700000
#define SCAN_BLOCK 1024
#define NB_MAX 512
#define NSEG  (NTOT + 1)

// ---------------- scratch (device globals; allocation-free) ----------------
__device__ float g_Id    [(size_t)NTOT * DIM];
__device__ float g_Id2   [(size_t)NTOT * DIM];
__device__ float g_IdAdj [(size_t)NTOT * DIM];
__device__ float g_Ft    [(size_t)NTOT * DIM];
__device__ float g_Ft2   [(size_t)NTOT * DIM];
__device__ float g_FtAdj [(size_t)NTOT * DIM];
__device__ float g_modal [(size_t)NTOT * DIM];
__device__ float g_tmpA  [(size_t)NTOT * DIM];   // also hosts GEMM L0/L1
__device__ float g_tmpB  [(size_t)NTOT * DIM];   // also hosts GEMM L2/L3

// fp16 gather tables
__device__ __half g_h_u     [(size_t)USERS * DIM];
__device__ __half g_h_i     [(size_t)ITEMS * DIM];
__device__ __half g_h_allID [(size_t)ITEMS * DIM];
__device__ __half g_h_allFt [(size_t)ITEMS * DIM];
__device__ __half g_h_Id    [(size_t)NTOT * DIM];
__device__ __half g_h_Ft    [(size_t)NTOT * DIM];
__device__ __half g_h_modal [(size_t)NTOT * DIM];
__device__ __half g_h_A     [(size_t)NTOT * DIM];

// batched CSR for 3 matrices (concatenated)
__device__ float2 g_cv_all [3 * EMAX];
__device__ int    g_rp     [3 * NSEG];
__device__ int    g_counts [3 * NSEG];
__device__ int    g_offs   [3 * NSEG];
__device__ int    g_bsums  [NB_MAX];

// ---------------- small utility kernels ----------------
__global__ void zero_int_kernel(int* __restrict__ p, int n) {
    int i = blockIdx.x * blockDim.x + threadIdx.x;
    if (i < n) p[i] = 0;
}

// both embedding tables -> fp16 in one launch
__global__ void f2h2_kernel(const float4* __restrict__ inU, const float4* __restrict__ inI,
                            uint2* __restrict__ outU, uint2* __restrict__ outI, int n4each) {
    int i = blockIdx.x * blockDim.x + threadIdx.x;
    if (i >= 2 * n4each) return;
    const float4* in = (i < n4each) ? inU : inI;
    uint2* o = (i < n4each) ? outU : outI;
    int j = (i < n4each) ? i : i - n4each;
    float4 v = in[j];
    __half2 h0 = __floats2half2_rn(v.x, v.y);
    __half2 h1 = __floats2half2_rn(v.z, v.w);
    uint2 r;
    r.x = *reinterpret_cast<uint32_t*>(&h0);
    r.y = *reinterpret_cast<uint32_t*>(&h1);
    o[j] = r;
}

// ---------------- batched counting sort: hist / scan / scatter ----------------
__global__ void hist3_kernel(const int* __restrict__ r0, const int* __restrict__ r1,
                             const int* __restrict__ r2, int n0, int n1, int n2,
                             int* __restrict__ counts) {
    int i = blockIdx.x * blockDim.x + threadIdx.x;
    int nt = n0 + n1 + n2;
    if (i >= nt) return;
    int row, seg;
    if (i < n0)            { seg = 0; row = r0[i]; }
    else if (i < n0 + n1)  { seg = 1; row = r1[i - n0]; }
    else                   { seg = 2; row = r2[i - n0 - n1]; }
    atomicAdd(&counts[seg * NSEG + row], 1);
}

__global__ void scan1_kernel(const int* __restrict__ counts, int* __restrict__ rowptr,
                             int* __restrict__ bsums, int n) {
    __shared__ int sh[SCAN_BLOCK];
    int g = blockIdx.x * SCAN_BLOCK + threadIdx.x;
    int v = (g < n) ? counts[g] : 0;
    sh[threadIdx.x] = v;
    __syncthreads();
    for (int off = 1; off < SCAN_BLOCK; off <<= 1) {
        int t = (threadIdx.x >= off) ? sh[threadIdx.x - off] : 0;
        __syncthreads();
        sh[threadIdx.x] += t;
        __syncthreads();
    }
    if (g < n) rowptr[g] = sh[threadIdx.x] - v;   // exclusive
    if (threadIdx.x == SCAN_BLOCK - 1) bsums[blockIdx.x] = sh[threadIdx.x];
}

__global__ void scan2_kernel(int* __restrict__ bsums, int nb) {
    __shared__ int sh[NB_MAX];
    int v = (threadIdx.x < nb) ? bsums[threadIdx.x] : 0;
    sh[threadIdx.x] = v;
    __syncthreads();
    for (int off = 1; off < NB_MAX; off <<= 1) {
        int t = (threadIdx.x >= off) ? sh[threadIdx.x - off] : 0;
        __syncthreads();
        sh[threadIdx.x] += t;
        __syncthreads();
    }
    if (threadIdx.x < nb) bsums[threadIdx.x] = sh[threadIdx.x] - v;  // exclusive
}

__global__ void scan3_kernel(int* __restrict__ rowptr, const int* __restrict__ bsums,
                             int* __restrict__ offs, int n) {
    int g = blockIdx.x * SCAN_BLOCK + threadIdx.x;
    if (g < n) {
        int v = rowptr[g] + bsums[blockIdx.x];
        rowptr[g] = v;
        offs[g] = v;
    }
}

__global__ void scatter3_kernel(const int* __restrict__ r0, const int* __restrict__ c0, const float* __restrict__ v0,
                                const int* __restrict__ r1, const int* __restrict__ c1, const float* __restrict__ v1,
                                const int* __restrict__ r2, const int* __restrict__ c2, const float* __restrict__ v2,
                                int n0, int n1, int n2,
                                int* __restrict__ offs, float2* __restrict__ cv) {
    int i = blockIdx.x * blockDim.x + threadIdx.x;
    int nt = n0 + n1 + n2;
    if (i >= nt) return;
    int row, seg, col; float val;
    if (i < n0)           { seg = 0; int j = i;            row = r0[j]; col = c0[j]; val = v0[j]; }
    else if (i < n0 + n1) { seg = 1; int j = i - n0;       row = r1[j]; col = c1[j]; val = v1[j]; }
    else                  { seg = 2; int j = i - n0 - n1;  row = r2[j]; col = c2[j]; val = v2[j]; }
    int pos = atomicAdd(&offs[seg * NSEG + row], 1);
    cv[pos] = make_float2(__int_as_float(col), val);
}

// ---------------- tf32 tensor-core GEMM with cp.async double buffering ----------------
__device__ __forceinline__ void mma_tf32(float c[4], uint32_t a0, uint32_t a1,
                                         uint32_t a2, uint32_t a3,
                                         uint32_t b0, uint32_t b1) {
    asm volatile(
        "mma.sync.aligned.m16n8k8.row.col.f32.tf32.tf32.f32 "
        "{%0,%1,%2,%3}, {%4,%5,%6,%7}, {%8,%9}, {%0,%1,%2,%3};"
        : "+f"(c[0]), "+f"(c[1]), "+f"(c[2]), "+f"(c[3])
        : "r"(a0), "r"(a1), "r"(a2), "r"(a3), "r"(b0), "r"(b1));
}

__device__ __forceinline__ void cp_async16(uint32_t smem_addr, const void* gsrc, int src_bytes) {
    asm volatile("cp.async.cg.shared.global [%0], [%1], 16, %2;"
                 :: "r"(smem_addr), "l"(gsrc), "r"(src_bytes));
}
__device__ __forceinline__ void cp_commit() {
    asm volatile("cp.async.commit_group;");
}
template <int N>
__device__ __forceinline__ void cp_wait() {
    asm volatile("cp.async.wait_group %0;" :: "n"(N));
}

#define AS_STRIDE 36
#define BS_STRIDE 132
#define AS_WORDS (128 * AS_STRIDE)     // 4608
#define BS_WORDS (32 * BS_STRIDE)      // 4224
#define GEMM_SMEM_WORDS (2 * (AS_WORDS + BS_WORDS))
#define GEMM_SMEM_BYTES (GEMM_SMEM_WORDS * 4)

__global__ __launch_bounds__(256, 2) void gemm4_kernel(
    const float* __restrict__ A0, const float* __restrict__ A1,
    const float* __restrict__ A2, const float* __restrict__ A3,
    const float* __restrict__ B0, const float* __restrict__ B1,
    const float* __restrict__ B2, const float* __restrict__ B3,
    float* __restrict__ L0, float* __restrict__ L1,
    float* __restrict__ L2, float* __restrict__ L3)
{
    extern __shared__ uint32_t smem[];
    uint32_t* As[2] = { smem, smem + AS_WORDS };
    uint32_t* Bs[2] = { smem + 2 * AS_WORDS, smem + 2 * AS_WORDS + BS_WORDS };

    int g = blockIdx.y;
    const float* A = (g == 0) ? A0 : (g == 1) ? A1 : (g == 2) ? A2 : A3;
    const float* B = (g == 0) ? B0 : (g == 1) ? B1 : (g == 2) ? B2 : B3;
    float*       L = (g == 0) ? L0 : (g == 1) ? L1 : (g == 2) ? L2 : L3;
    int K = (g & 1) ? 768 : 1024;
    const int M = ITEMS;
    int nIter = K >> 5;

    int tid = threadIdx.x;
    int wid = tid >> 5;
    int lane = tid & 31;
    int grp = lane >> 2;
    int tig = lane & 3;
    int warp_m = wid & 1;
    int warp_n = wid >> 1;
    int blockRow = blockIdx.x * 128;

    int a_row[4], a_kq[4], b_row[4], b_nq[4];
#pragma unroll
    for (int t = 0; t < 4; t++) {
        int idx = tid + t * 256;
        a_row[t] = idx >> 3;  a_kq[t] = (idx & 7) << 2;
        b_row[t] = idx >> 5;  b_nq[t] = (idx & 31) << 2;
    }

    auto load_stage = [&](int it, int buf) {
        int k0 = it << 5;
#pragma unroll
        for (int t = 0; t < 4; t++) {
            int gm = blockRow + a_row[t];
            uint32_t dst = (uint32_t)__cvta_generic_to_shared(&As[buf][a_row[t] * AS_STRIDE + a_kq[t]]);
            const float* src = A + (size_t)gm * K + k0 + a_kq[t];
            cp_async16(dst, src, (gm < M) ? 16 : 0);
        }
#pragma unroll
        for (int t = 0; t < 4; t++) {
            uint32_t dst = (uint32_t)__cvta_generic_to_shared(&Bs[buf][b_row[t] * BS_STRIDE + b_nq[t]]);
            const float* src = B + (size_t)(k0 + b_row[t]) * 128 + b_nq[t];
            cp_async16(dst, src, 16);
        }
        cp_commit();
    };

    float c[4][4][4];
#pragma unroll
    for (int mt = 0; mt < 4; mt++)
#pragma unroll
        for (int nt = 0; nt < 4; nt++)
#pragma unroll
            for (int f = 0; f < 4; f++) c[mt][nt][f] = 0.f;

    load_stage(0, 0);

    for (int it = 0; it < nIter; it++) {
        int cur = it & 1;
        if (it + 1 < nIter) {
            load_stage(it + 1, cur ^ 1);
            cp_wait<1>();
        } else {
            cp_wait<0>();
        }
        __syncthreads();

        uint32_t* as = As[cur];
        uint32_t* bs = Bs[cur];
#pragma unroll
        for (int ks = 0; ks < 4; ks++) {
            int kb = ks * 8;
            uint32_t a[4][4];
#pragma unroll
            for (int mt = 0; mt < 4; mt++) {
                int mb = warp_m * 64 + mt * 16;
                a[mt][0] = as[(mb + grp)     * AS_STRIDE + kb + tig];
                a[mt][1] = as[(mb + grp + 8) * AS_STRIDE + kb + tig];
                a[mt][2] = as[(mb + grp)     * AS_STRIDE + kb + tig + 4];
                a[mt][3] = as[(mb + grp + 8) * AS_STRIDE + kb + tig + 4];
            }
            uint32_t b[4][2];
#pragma unroll
            for (int nt = 0; nt < 4; nt++) {
                int nb = warp_n * 32 + nt * 8;
                b[nt][0] = bs[(kb + tig)     * BS_STRIDE + nb + grp];
                b[nt][1] = bs[(kb + tig + 4) * BS_STRIDE + nb + grp];
            }
#pragma unroll
            for (int mt = 0; mt < 4; mt++)
#pragma unroll
                for (int nt = 0; nt < 4; nt++)
                    mma_tf32(c[mt][nt], a[mt][0], a[mt][1], a[mt][2], a[mt][3],
                             b[nt][0], b[nt][1]);
        }
        __syncthreads();
    }

#pragma unroll
    for (int mt = 0; mt < 4; mt++) {
        int row0 = blockRow + warp_m * 64 + mt * 16 + grp;
        int row1 = row0 + 8;
#pragma unroll
        for (int nt = 0; nt < 4; nt++) {
            int col = warp_n * 32 + nt * 8 + 2 * tig;
            float v0 = c[mt][nt][0], v1 = c[mt][nt][1];
            float v2 = c[mt][nt][2], v3 = c[mt][nt][3];
            v0 = (v0 > 0.f) ? v0 : 0.2f * v0;
            v1 = (v1 > 0.f) ? v1 : 0.2f * v1;
            v2 = (v2 > 0.f) ? v2 : 0.2f * v2;
            v3 = (v3 > 0.f) ? v3 : 0.2f * v3;
            if (row0 < M) *(float2*)(L + (size_t)row0 * 128 + col) = make_float2(v0, v1);
            if (row1 < M) *(float2*)(L + (size_t)row1 * 128 + col) = make_float2(v2, v3);
        }
    }
}

// ---------------- half write helper ----------------
__device__ __forceinline__ void store_h4(__half* base, size_t row, int lane, float4 v) {
    __half2 h0 = __floats2half2_rn(v.x, v.y);
    __half2 h1 = __floats2half2_rn(v.z, v.w);
    uint2 r;
    r.x = *reinterpret_cast<uint32_t*>(&h0);
    r.y = *reinterpret_cast<uint32_t*>(&h1);
    *((uint2*)(base + row * DIM) + lane) = r;
}

// ---------------- weighted combine + l2norm, both pairs in one launch ----------------
__global__ void combine_l2norm2_kernel(const float* __restrict__ La0, const float* __restrict__ Lb0,
                                       const float* __restrict__ La1, const float* __restrict__ Lb1,
                                       const float* __restrict__ mw,
                                       __half* __restrict__ out0, __half* __restrict__ out1,
                                       int nrows)
{
    int wid = (blockIdx.x * blockDim.x + threadIdx.x) >> 5;
    int lane = threadIdx.x & 31;
    if (wid >= nrows) return;
    const float* La = blockIdx.y ? La1 : La0;
    const float* Lb = blockIdx.y ? Lb1 : Lb0;
    __half* outh = blockIdx.y ? out1 : out0;
    float m0 = mw[0], m1 = mw[1];
    float mx = fmaxf(m0, m1);
    float e0 = __expf(m0 - mx), e1 = __expf(m1 - mx);
    float w0 = e0 / (e0 + e1), w1 = e1 / (e0 + e1);
    size_t off = (size_t)wid * DIM + lane * 4;
    float4 a = *(const float4*)(La + off);
    float4 b = *(const float4*)(Lb + off);
    float4 v;
    v.x = w0 * a.x + w1 * b.x;
    v.y = w0 * a.y + w1 * b.y;
    v.z = w0 * a.z + w1 * b.z;
    v.w = w0 * a.w + w1 * b.w;
    float s = v.x * v.x + v.y * v.y + v.z * v.z + v.w * v.w;
#pragma unroll
    for (int o = 16; o > 0; o >>= 1) s += __shfl_xor_sync(0xffffffffu, s, o);
    float inv = 1.f / fmaxf(sqrtf(s), 1e-12f);
    v.x *= inv; v.y *= inv; v.z *= inv; v.w *= inv;
    store_h4(outh, wid, lane, v);
}

// ---------------- fp16-gather CSR SpMM (warp per row) ----------------
__device__ __forceinline__ float4 gfetch_h(int col, int lane,
                                           const __half* __restrict__ xU,
                                           const __half* __restrict__ xI) {
    const __half* x = (col < USERS) ? (xU + (size_t)col * DIM)
                                    : (xI + (size_t)(col - USERS) * DIM);
    uint2 raw = __ldg((const uint2*)x + lane);
    __half2 h0 = *reinterpret_cast<__half2*>(&raw.x);
    __half2 h1 = *reinterpret_cast<__half2*>(&raw.y);
    float2 f0 = __half22float2(h0), f1 = __half22float2(h1);
    return make_float4(f0.x, f0.y, f1.x, f1.y);
}
__device__ __forceinline__ void facc(float4& a, float w, float4 x) {
    a.x += w * x.x; a.y += w * x.y; a.z += w * x.z; a.w += w * x.w;
}

// single-table spmm (optionally fp16 out)
__global__ void spmm_h_kernel(const int* __restrict__ rowptr, const float2* __restrict__ cv,
                              const __half* __restrict__ xU, const __half* __restrict__ xI,
                              float* __restrict__ out, __half* __restrict__ outh)
{
    int row = blockIdx.x * 8 + (threadIdx.x >> 5);
    int lane = threadIdx.x & 31;
    if (row >= NTOT) return;
    int s = rowptr[row], e = rowptr[row + 1];
    float4 acc = make_float4(0.f, 0.f, 0.f, 0.f);
    int i = s;
    for (; i + 4 <= e; i += 4) {
        float2 c0 = cv[i], c1 = cv[i + 1], c2 = cv[i + 2], c3 = cv[i + 3];
        float4 x0 = gfetch_h(__float_as_int(c0.x), lane, xU, xI);
        float4 x1 = gfetch_h(__float_as_int(c1.x), lane, xU, xI);
        float4 x2 = gfetch_h(__float_as_int(c2.x), lane, xU, xI);
        float4 x3 = gfetch_h(__float_as_int(c3.x), lane, xU, xI);
        facc(acc, c0.y, x0); facc(acc, c1.y, x1);
        facc(acc, c2.y, x2); facc(acc, c3.y, x3);
    }
    for (; i < e; i++) {
        float2 c0 = cv[i];
        float4 x0 = gfetch_h(__float_as_int(c0.x), lane, xU, xI);
        facc(acc, c0.y, x0);
    }
    *((float4*)(out + (size_t)row * DIM) + lane) = acc;
    if (outh) store_h4(outh, row, lane, acc);
}

// two independent single-table spmms (same gather tables) in one launch
__global__ void spmm_h_pair_kernel(const int* __restrict__ rp0, const int* __restrict__ rp1,
                                   const float2* __restrict__ cv,
                                   const __half* __restrict__ xU, const __half* __restrict__ xI,
                                   float* __restrict__ out0, float* __restrict__ out1)
{
    int row = blockIdx.x * 8 + (threadIdx.x >> 5);
    int lane = threadIdx.x & 31;
    if (row >= NTOT) return;
    const int* rowptr = blockIdx.y ? rp1 : rp0;
    float* out = blockIdx.y ? out1 : out0;
    int s = rowptr[row], e = rowptr[row + 1];
    float4 acc = make_float4(0.f, 0.f, 0.f, 0.f);
    int i = s;
    for (; i + 4 <= e; i += 4) {
        float2 c0 = cv[i], c1 = cv[i + 1], c2 = cv[i + 2], c3 = cv[i + 3];
        float4 x0 = gfetch_h(__float_as_int(c0.x), lane, xU, xI);
        float4 x1 = gfetch_h(__float_as_int(c1.x), lane, xU, xI);
        float4 x2 = gfetch_h(__float_as_int(c2.x), lane, xU, xI);
        float4 x3 = gfetch_h(__float_as_int(c3.x), lane, xU, xI);
        facc(acc, c0.y, x0); facc(acc, c1.y, x1);
        facc(acc, c2.y, x2); facc(acc, c3.y, x3);
    }
    for (; i < e; i++) {
        float2 c0 = cv[i];
        float4 x0 = gfetch_h(__float_as_int(c0.x), lane, xU, xI);
        facc(acc, c0.y, x0);
    }
    *((float4*)(out + (size_t)row * DIM) + lane) = acc;
}

// Dual SpMM, shared USER table, 4x unrolled; fp32+fp16 outs.
__global__ void spmm_h_dualU_kernel(const int* __restrict__ rowptr, const float2* __restrict__ cv,
                                    const __half* __restrict__ xU,
                                    const __half* __restrict__ xIa, const __half* __restrict__ xIb,
                                    float* __restrict__ outA, float* __restrict__ outB,
                                    __half* __restrict__ outAh, __half* __restrict__ outBh)
{
    int row = blockIdx.x * 8 + (threadIdx.x >> 5);
    int lane = threadIdx.x & 31;
    if (row >= NTOT) return;
    int s = rowptr[row], e = rowptr[row + 1];
    float4 accA = make_float4(0.f, 0.f, 0.f, 0.f);
    float4 accB = make_float4(0.f, 0.f, 0.f, 0.f);
    int i = s;
    for (; i + 4 <= e; i += 4) {
        float2 cc[4];
        float4 xa[4], xb[4];
#pragma unroll
        for (int u = 0; u < 4; u++) cc[u] = cv[i + u];
#pragma unroll
        for (int u = 0; u < 4; u++) {
            int col = __float_as_int(cc[u].x);
            if (col < USERS) {
                xa[u] = gfetch_h(col, lane, xU, xU);
                xb[u] = xa[u];
            } else {
                xa[u] = gfetch_h(col, lane, xU, xIa);
                xb[u] = gfetch_h(col, lane, xU, xIb);
            }
        }
#pragma unroll
        for (int u = 0; u < 4; u++) {
            facc(accA, cc[u].y, xa[u]);
            facc(accB, cc[u].y, xb[u]);
        }
    }
    for (; i < e; i++) {
        float2 c = cv[i];
        int col = __float_as_int(c.x);
        float4 xa, xb;
        if (col < USERS) { xa = gfetch_h(col, lane, xU, xU); xb = xa; }
        else { xa = gfetch_h(col, lane, xU, xIa); xb = gfetch_h(col, lane, xU, xIb); }
        facc(accA, c.y, xa); facc(accB, c.y, xb);
    }
    *((float4*)(outA + (size_t)row * DIM) + lane) = accA;
    *((float4*)(outB + (size_t)row * DIM) + lane) = accB;
    store_h4(outAh, row, lane, accA);
    store_h4(outBh, row, lane, accB);
}

// Dual SpMM, shared ITEM table, 4x unrolled.
__global__ void spmm_h_dualI_kernel(const int* __restrict__ rowptr, const float2* __restrict__ cv,
                                    const __half* __restrict__ xUa, const __half* __restrict__ xUb,
                                    const __half* __restrict__ xI,
                                    float* __restrict__ outA, float* __restrict__ outB)
{
    int row = blockIdx.x * 8 + (threadIdx.x >> 5);
    int lane = threadIdx.x & 31;
    if (row >= NTOT) return;
    int s = rowptr[row], e = rowptr[row + 1];
    float4 accA = make_float4(0.f, 0.f, 0.f, 0.f);
    float4 accB = make_float4(0.f, 0.f, 0.f, 0.f);
    int i = s;
    for (; i + 4 <= e; i += 4) {
        float2 cc[4];
        float4 xa[4], xb[4];
#pragma unroll
        for (int u = 0; u < 4; u++) cc[u] = cv[i + u];
#pragma unroll
        for (int u = 0; u < 4; u++) {
            int col = __float_as_int(cc[u].x);
            if (col < USERS) {
                xa[u] = gfetch_h(col, lane, xUa, xUa);
                xb[u] = gfetch_h(col, lane, xUb, xUb);
            } else {
                xa[u] = gfetch_h(col, lane, xUa, xI);
                xb[u] = xa[u];
            }
        }
#pragma unroll
        for (int u = 0; u < 4; u++) {
            facc(accA, cc[u].y, xa[u]);
            facc(accB, cc[u].y, xb[u]);
        }
    }
    for (; i < e; i++) {
        float2 c = cv[i];
        int col = __float_as_int(c.x);
        float4 xa, xb;
        if (col < USERS) { xa = gfetch_h(col, lane, xUa, xUa); xb = gfetch_h(col, lane, xUb, xUb); }
        else { xa = gfetch_h(col, lane, xUa, xI); xb = xa; }
        facc(accA, c.y, xa); facc(accB, c.y, xb);
    }
    *((float4*)(outA + (size_t)row * DIM) + lane) = accA;
    *((float4*)(outB + (size_t)row * DIM) + lane) = accB;
}

// ---------------- combine into modal (fp32 + fp16) ----------------
__global__ void combine_kernel(const float4* __restrict__ id, const float4* __restrict__ id2,
                               const float4* __restrict__ idadj,
                               const float4* __restrict__ ft, const float4* __restrict__ ft2,
                               const float4* __restrict__ ftadj,
                               float4* __restrict__ modal, __half* __restrict__ modalh, int n4)
{
    int i = blockIdx.x * blockDim.x + threadIdx.x;
    if (i >= n4) return;
    float4 a = id[i], b = id2[i], c = idadj[i];
    float4 d = ft[i], e = ft2[i], f = ftadj[i];
    float4 m;
    m.x = 0.5f * (a.x + b.x + 0.2f * c.x) + 0.5f * (d.x + e.x + 0.2f * f.x);
    m.y = 0.5f * (a.y + b.y + 0.2f * c.y) + 0.5f * (d.y + e.y + 0.2f * f.y);
    m.z = 0.5f * (a.z + b.z + 0.2f * c.z) + 0.5f * (d.z + e.z + 0.2f * f.z);
    m.w = 0.5f * (a.w + b.w + 0.2f * c.w) + 0.5f * (d.w + e.w + 0.2f * f.w);
    modal[i] = m;
    __half2 h0 = __floats2half2_rn(m.x, m.y);
    __half2 h1 = __floats2half2_rn(m.z, m.w);
    uint2 r;
    r.x = *reinterpret_cast<uint32_t*>(&h0);
    r.y = *reinterpret_cast<uint32_t*>(&h1);
    ((uint2*)modalh)[i] = r;
}

// ---------------- final: out = modal + A + B + 0.5 * l2norm(modal) ----------------
__global__ void final_kernel(const float* __restrict__ modal, const float* __restrict__ A,
                             const float* __restrict__ B, float* __restrict__ out, int nrows)
{
    int wid = (blockIdx.x * blockDim.x + threadIdx.x) >> 5;
    int lane = threadIdx.x & 31;
    if (wid >= nrows) return;
    size_t off = (size_t)wid * DIM + lane * 4;
    float4 m = *(const float4*)(modal + off);
    float4 a = *(const float4*)(A + off);
    float4 b = *(const float4*)(B + off);
    float s = m.x * m.x + m.y * m.y + m.z * m.z + m.w * m.w;
#pragma unroll
    for (int o = 16; o > 0; o >>= 1) s += __shfl_xor_sync(0xffffffffu, s, o);
    float inv = 0.5f / fmaxf(sqrtf(s), 1e-12f);   // RIS_LAMBDA / norm
    float4 r;
    r.x = m.x + a.x + b.x + inv * m.x;
    r.y = m.y + a.y + b.y + inv * m.y;
    r.z = m.z + a.z + b.z + inv * m.z;
    r.w = m.w + a.w + b.w + inv * m.w;
    *(float4*)(out + off) = r;
}

// ---------------- host ----------------
extern "C" void kernel_launch(void* const* d_in, const int* in_sizes, int n_in,
                              void* d_out, int out_size)
{
    const int*   adj_rows = (const int*)d_in[0];
    const int*   adj_cols = (const int*)d_in[1];
    const float* adj_vals = (const float*)d_in[2];
    const int*   id_rows  = (const int*)d_in[3];
    const int*   id_cols  = (const int*)d_in[4];
    const float* id_vals  = (const float*)d_in[5];
    const int*   ft_rows  = (const int*)d_in[6];
    const int*   ft_cols  = (const int*)d_in[7];
    const float* ft_vals  = (const float*)d_in[8];
    const float* uEmb     = (const float*)d_in[9];
    const float* iEmb     = (const float*)d_in[10];
    const float* img_emb  = (const float*)d_in[11];
    const float* img_id   = (const float*)d_in[12];
    const float* txt_emb  = (const float*)d_in[13];
    const float* txt_id   = (const float*)d_in[14];
    const float* img_tr   = (const float*)d_in[15];
    const float* img_id_tr= (const float*)d_in[16];
    const float* txt_tr   = (const float*)d_in[17];
    const float* txt_id_tr= (const float*)d_in[18];
    const float* mw       = (const float*)d_in[19];
    float* out = (float*)d_out;

    int E_adj = in_sizes[0];
    int E_id  = in_sizes[3];
    int E_ft  = in_sizes[6];
    int E_tot = E_adj + E_id + E_ft;

    float *pId, *pId2, *pIdAdj, *pFt, *pFt2, *pFtAdj, *pModal, *pA, *pB;
    __half *hU, *hI, *hAllID, *hAllFt, *hId, *hFt, *hModal, *hA;
    float2 *cvAll;
    int *pRp, *pCounts, *pOffs, *pBsums;
    cudaGetSymbolAddress((void**)&pId,     g_Id);
    cudaGetSymbolAddress((void**)&pId2,    g_Id2);
    cudaGetSymbolAddress((void**)&pIdAdj,  g_IdAdj);
    cudaGetSymbolAddress((void**)&pFt,     g_Ft);
    cudaGetSymbolAddress((void**)&pFt2,    g_Ft2);
    cudaGetSymbolAddress((void**)&pFtAdj,  g_FtAdj);
    cudaGetSymbolAddress((void**)&pModal,  g_modal);
    cudaGetSymbolAddress((void**)&pA,      g_tmpA);
    cudaGetSymbolAddress((void**)&pB,      g_tmpB);
    cudaGetSymbolAddress((void**)&hU,      g_h_u);
    cudaGetSymbolAddress((void**)&hI,      g_h_i);
    cudaGetSymbolAddress((void**)&hAllID,  g_h_allID);
    cudaGetSymbolAddress((void**)&hAllFt,  g_h_allFt);
    cudaGetSymbolAddress((void**)&hId,     g_h_Id);
    cudaGetSymbolAddress((void**)&hFt,     g_h_Ft);
    cudaGetSymbolAddress((void**)&hModal,  g_h_modal);
    cudaGetSymbolAddress((void**)&hA,      g_h_A);
    cudaGetSymbolAddress((void**)&cvAll,   g_cv_all);
    cudaGetSymbolAddress((void**)&pRp,     g_rp);
    cudaGetSymbolAddress((void**)&pCounts, g_counts);
    cudaGetSymbolAddress((void**)&pOffs,   g_offs);
    cudaGetSymbolAddress((void**)&pBsums,  g_bsums);

    // one-time host-side resources (streams/events for fork-join; capture-safe reuse)
    static cudaStream_t s1 = nullptr;
    static cudaEvent_t evFork = nullptr, evGemmDone = nullptr;
    static bool inited = false;
    if (!inited) {
        cudaStreamCreateWithFlags(&s1, cudaStreamNonBlocking);
        cudaEventCreateWithFlags(&evFork, cudaEventDisableTiming);
        cudaEventCreateWithFlags(&evGemmDone, cudaEventDisableTiming);
        cudaFuncSetAttribute(gemm4_kernel, cudaFuncAttributeMaxDynamicSharedMemorySize,
                             GEMM_SMEM_BYTES);
        inited = true;
    }

    // GEMM lrelu buffers live in g_tmpA/g_tmpB (free until GNN layers)
    float* L_imgid = pA;
    float* L_txtid = pA + (size_t)ITEMS * DIM;
    float* L_img   = pB;
    float* L_txt   = pB + (size_t)ITEMS * DIM;

    // ---- fork: GEMM arm on s1, sparse arm on stream 0 ----
    cudaEventRecord(evFork, 0);
    cudaStreamWaitEvent(s1, evFork, 0);

    // s1: modality GEMMs + weighted-combine/l2norm (tensor/DRAM-bound arm)
    {
        dim3 ggrid((ITEMS + 127) / 128, 4);
        gemm4_kernel<<<ggrid, 256, GEMM_SMEM_BYTES, s1>>>(
            img_id, txt_id, img_emb, txt_emb,
            img_id_tr, txt_id_tr, img_tr, txt_tr,
            L_imgid, L_txtid, L_img, L_txt);
        dim3 cgrid((ITEMS * 32 + 255) / 256, 2);
        combine_l2norm2_kernel<<<cgrid, 256, 0, s1>>>(L_imgid, L_txtid, L_img, L_txt,
                                                      mw, hAllID, hAllFt, ITEMS);
        cudaEventRecord(evGemmDone, s1);
    }

    // stream 0: batched CSR build (L2/atomic-bound arm)
    {
        int n = 3 * NSEG;
        int nb = (n + SCAN_BLOCK - 1) / SCAN_BLOCK;
        zero_int_kernel<<<(n + 255) / 256, 256>>>(pCounts, n);
        hist3_kernel<<<(E_tot + 255) / 256, 256>>>(adj_rows, id_rows, ft_rows,
                                                   E_adj, E_id, E_ft, pCounts);
        scan1_kernel<<<nb, SCAN_BLOCK>>>(pCounts, pRp, pBsums, n);
        scan2_kernel<<<1, NB_MAX>>>(pBsums, nb);
        scan3_kernel<<<nb, SCAN_BLOCK>>>(pRp, pBsums, pOffs, n);
        scatter3_kernel<<<(E_tot + 255) / 256, 256>>>(adj_rows, adj_cols, adj_vals,
                                                      id_rows, id_cols, id_vals,
                                                      ft_rows, ft_cols, ft_vals,
                                                      E_adj, E_id, E_ft, pOffs, cvAll);
    }
    const int* rpAdj = pRp;
    const int* rpId  = pRp + NSEG;
    const int* rpFt  = pRp + 2 * NSEG;

    // stream 0: fp16 input tables, then the two input-only spmms (overlap GEMM)
    {
        int n4u = USERS * DIM / 4;
        f2h2_kernel<<<(2 * n4u + 255) / 256, 256>>>((const float4*)uEmb, (const float4*)iEmb,
                                                    (uint2*)hU, (uint2*)hI, n4u);
    }
    int spmm_blocks = (NTOT + 7) / 8;
    {
        dim3 pgrid(spmm_blocks, 2);
        spmm_h_pair_kernel<<<pgrid, 256>>>(rpId, rpFt, cvAll, hU, hI, pIdAdj, pFtAdj);
    }

    // ---- join: need hAllID/hAllFt from s1 before dualU ----
    cudaStreamWaitEvent(0, evGemmDone, 0);

    spmm_h_dualU_kernel<<<spmm_blocks, 256>>>(rpAdj, cvAll, hU, hAllID, hAllFt,
                                              pId, pFt, hId, hFt);
    spmm_h_dualI_kernel<<<spmm_blocks, 256>>>(rpAdj, cvAll, hId, hFt, hI, pId2, pFt2);

    int n4 = (int)(((size_t)NTOT * DIM) / 4);
    combine_kernel<<<(n4 + 255) / 256, 256>>>((float4*)pId, (float4*)pId2, (float4*)pIdAdj,
                                              (float4*)pFt, (float4*)pFt2, (float4*)pFtAdj,
                                              (float4*)pModal, hModal, n4);

    // 2-layer GNN propagation (overwrites g_tmpA/g_tmpB; GEMM buffers consumed)
    spmm_h_kernel<<<spmm_blocks, 256>>>(rpAdj, cvAll, hModal, hModal + (size_t)USERS * DIM, pA, hA);
    spmm_h_kernel<<<spmm_blocks, 256>>>(rpAdj, cvAll, hA, hA + (size_t)USERS * DIM, pB, nullptr);

    // final
    int fin_blocks = (NTOT * 32 + 255) / 256;
    final_kernel<<<fin_blocks, 256>>>(pModal, pA, pB, out, NTOT);

    (void)n_in; (void)out_size;
}

// round 8
// speedup vs baseline: 4.1250x; 1.0403x over previous
#include <cuda_runtime.h>
#include <cuda_fp16.h>
#include <cstdint>
#include <cstddef>

#define USERS 50000
#define ITEMS 50000
#define NTOT  100000
#define DIM   128
#define EMAX  1700000
#define SCAN_BLOCK 1024
#define NB_MAX 512
#define NSEG  (NTOT + 1)

// ---------------- scratch (device globals; allocation-free) ----------------
__device__ float g_IdAdj [(size_t)NTOT * DIM];
__device__ float g_FtAdj [(size_t)NTOT * DIM];
__device__ float g_modal [(size_t)NTOT * DIM];
__device__ float g_tmpA  [(size_t)NTOT * DIM];   // GNN layer1 out; also GEMM L0/L1
__device__ float g_tmpB  [(size_t)NTOT * DIM];   // GEMM L2/L3 only

// fp16 gather tables
__device__ __half g_h_u     [(size_t)USERS * DIM];
__device__ __half g_h_i     [(size_t)ITEMS * DIM];
__device__ __half g_h_allID [(size_t)ITEMS * DIM];
__device__ __half g_h_allFt [(size_t)ITEMS * DIM];
__device__ __half g_h_Id    [(size_t)NTOT * DIM];
__device__ __half g_h_Ft    [(size_t)NTOT * DIM];
__device__ __half g_h_modal [(size_t)NTOT * DIM];
__device__ __half g_h_A     [(size_t)NTOT * DIM];

// batched CSR for 3 matrices (concatenated)
__device__ float2 g_cv_all [3 * EMAX];
__device__ int    g_rp     [3 * NSEG];
__device__ int    g_counts [3 * NSEG];
__device__ int    g_offs   [3 * NSEG];
__device__ int    g_bsums  [NB_MAX];

// ---------------- small utility kernels ----------------
__global__ void zero_int_kernel(int* __restrict__ p, int n) {
    int i = blockIdx.x * blockDim.x + threadIdx.x;
    if (i < n) p[i] = 0;
}

// both embedding tables -> fp16 in one launch
__global__ void f2h2_kernel(const float4* __restrict__ inU, const float4* __restrict__ inI,
                            uint2* __restrict__ outU, uint2* __restrict__ outI, int n4each) {
    int i = blockIdx.x * blockDim.x + threadIdx.x;
    if (i >= 2 * n4each) return;
    const float4* in = (i < n4each) ? inU : inI;
    uint2* o = (i < n4each) ? outU : outI;
    int j = (i < n4each) ? i : i - n4each;
    float4 v = in[j];
    __half2 h0 = __floats2half2_rn(v.x, v.y);
    __half2 h1 = __floats2half2_rn(v.z, v.w);
    uint2 r;
    r.x = *reinterpret_cast<uint32_t*>(&h0);
    r.y = *reinterpret_cast<uint32_t*>(&h1);
    o[j] = r;
}

// ---------------- batched counting sort: hist / scan / scatter ----------------
__global__ void hist3_kernel(const int* __restrict__ r0, const int* __restrict__ r1,
                             const int* __restrict__ r2, int n0, int n1, int n2,
                             int* __restrict__ counts) {
    int i = blockIdx.x * blockDim.x + threadIdx.x;
    int nt = n0 + n1 + n2;
    if (i >= nt) return;
    int row, seg;
    if (i < n0)            { seg = 0; row = r0[i]; }
    else if (i < n0 + n1)  { seg = 1; row = r1[i - n0]; }
    else                   { seg = 2; row = r2[i - n0 - n1]; }
    atomicAdd(&counts[seg * NSEG + row], 1);
}

__global__ void scan1_kernel(const int* __restrict__ counts, int* __restrict__ rowptr,
                             int* __restrict__ bsums, int n) {
    __shared__ int sh[SCAN_BLOCK];
    int g = blockIdx.x * SCAN_BLOCK + threadIdx.x;
    int v = (g < n) ? counts[g] : 0;
    sh[threadIdx.x] = v;
    __syncthreads();
    for (int off = 1; off < SCAN_BLOCK; off <<= 1) {
        int t = (threadIdx.x >= off) ? sh[threadIdx.x - off] : 0;
        __syncthreads();
        sh[threadIdx.x] += t;
        __syncthreads();
    }
    if (g < n) rowptr[g] = sh[threadIdx.x] - v;   // exclusive
    if (threadIdx.x == SCAN_BLOCK - 1) bsums[blockIdx.x] = sh[threadIdx.x];
}

__global__ void scan2_kernel(int* __restrict__ bsums, int nb) {
    __shared__ int sh[NB_MAX];
    int v = (threadIdx.x < nb) ? bsums[threadIdx.x] : 0;
    sh[threadIdx.x] = v;
    __syncthreads();
    for (int off = 1; off < NB_MAX; off <<= 1) {
        int t = (threadIdx.x >= off) ? sh[threadIdx.x - off] : 0;
        __syncthreads();
        sh[threadIdx.x] += t;
        __syncthreads();
    }
    if (threadIdx.x < nb) bsums[threadIdx.x] = sh[threadIdx.x] - v;  // exclusive
}

__global__ void scan3_kernel(int* __restrict__ rowptr, const int* __restrict__ bsums,
                             int* __restrict__ offs, int n) {
    int g = blockIdx.x * SCAN_BLOCK + threadIdx.x;
    if (g < n) {
        int v = rowptr[g] + bsums[blockIdx.x];
        rowptr[g] = v;
        offs[g] = v;
    }
}

__global__ void scatter3_kernel(const int* __restrict__ r0, const int* __restrict__ c0, const float* __restrict__ v0,
                                const int* __restrict__ r1, const int* __restrict__ c1, const float* __restrict__ v1,
                                const int* __restrict__ r2, const int* __restrict__ c2, const float* __restrict__ v2,
                                int n0, int n1, int n2,
                                int* __restrict__ offs, float2* __restrict__ cv) {
    int i = blockIdx.x * blockDim.x + threadIdx.x;
    int nt = n0 + n1 + n2;
    if (i >= nt) return;
    int row, seg, col; float val;
    if (i < n0)           { seg = 0; int j = i;            row = r0[j]; col = c0[j]; val = v0[j]; }
    else if (i < n0 + n1) { seg = 1; int j = i - n0;       row = r1[j]; col = c1[j]; val = v1[j]; }
    else                  { seg = 2; int j = i - n0 - n1;  row = r2[j]; col = c2[j]; val = v2[j]; }
    int pos = atomicAdd(&offs[seg * NSEG + row], 1);
    cv[pos] = make_float2(__int_as_float(col), val);
}

// ---------------- tf32 tensor-core GEMM with cp.async double buffering ----------------
__device__ __forceinline__ void mma_tf32(float c[4], uint32_t a0, uint32_t a1,
                                         uint32_t a2, uint32_t a3,
                                         uint32_t b0, uint32_t b1) {
    asm volatile(
        "mma.sync.aligned.m16n8k8.row.col.f32.tf32.tf32.f32 "
        "{%0,%1,%2,%3}, {%4,%5,%6,%7}, {%8,%9}, {%0,%1,%2,%3};"
        : "+f"(c[0]), "+f"(c[1]), "+f"(c[2]), "+f"(c[3])
        : "r"(a0), "r"(a1), "r"(a2), "r"(a3), "r"(b0), "r"(b1));
}

__device__ __forceinline__ void cp_async16(uint32_t smem_addr, const void* gsrc, int src_bytes) {
    asm volatile("cp.async.cg.shared.global [%0], [%1], 16, %2;"
                 :: "r"(smem_addr), "l"(gsrc), "r"(src_bytes));
}
__device__ __forceinline__ void cp_commit() {
    asm volatile("cp.async.commit_group;");
}
template <int N>
__device__ __forceinline__ void cp_wait() {
    asm volatile("cp.async.wait_group %0;" :: "n"(N));
}

#define AS_STRIDE 36
#define BS_STRIDE 132
#define AS_WORDS (128 * AS_STRIDE)
#define BS_WORDS (32 * BS_STRIDE)
#define GEMM_SMEM_WORDS (2 * (AS_WORDS + BS_WORDS))
#define GEMM_SMEM_BYTES (GEMM_SMEM_WORDS * 4)

__global__ __launch_bounds__(256, 2) void gemm4_kernel(
    const float* __restrict__ A0, const float* __restrict__ A1,
    const float* __restrict__ A2, const float* __restrict__ A3,
    const float* __restrict__ B0, const float* __restrict__ B1,
    const float* __restrict__ B2, const float* __restrict__ B3,
    float* __restrict__ L0, float* __restrict__ L1,
    float* __restrict__ L2, float* __restrict__ L3)
{
    extern __shared__ uint32_t smem[];
    uint32_t* As[2] = { smem, smem + AS_WORDS };
    uint32_t* Bs[2] = { smem + 2 * AS_WORDS, smem + 2 * AS_WORDS + BS_WORDS };

    int g = blockIdx.y;
    const float* A = (g == 0) ? A0 : (g == 1) ? A1 : (g == 2) ? A2 : A3;
    const float* B = (g == 0) ? B0 : (g == 1) ? B1 : (g == 2) ? B2 : B3;
    float*       L = (g == 0) ? L0 : (g == 1) ? L1 : (g == 2) ? L2 : L3;
    int K = (g & 1) ? 768 : 1024;
    const int M = ITEMS;
    int nIter = K >> 5;

    int tid = threadIdx.x;
    int wid = tid >> 5;
    int lane = tid & 31;
    int grp = lane >> 2;
    int tig = lane & 3;
    int warp_m = wid & 1;
    int warp_n = wid >> 1;
    int blockRow = blockIdx.x * 128;

    int a_row[4], a_kq[4], b_row[4], b_nq[4];
#pragma unroll
    for (int t = 0; t < 4; t++) {
        int idx = tid + t * 256;
        a_row[t] = idx >> 3;  a_kq[t] = (idx & 7) << 2;
        b_row[t] = idx >> 5;  b_nq[t] = (idx & 31) << 2;
    }

    auto load_stage = [&](int it, int buf) {
        int k0 = it << 5;
#pragma unroll
        for (int t = 0; t < 4; t++) {
            int gm = blockRow + a_row[t];
            uint32_t dst = (uint32_t)__cvta_generic_to_shared(&As[buf][a_row[t] * AS_STRIDE + a_kq[t]]);
            const float* src = A + (size_t)gm * K + k0 + a_kq[t];
            cp_async16(dst, src, (gm < M) ? 16 : 0);
        }
#pragma unroll
        for (int t = 0; t < 4; t++) {
            uint32_t dst = (uint32_t)__cvta_generic_to_shared(&Bs[buf][b_row[t] * BS_STRIDE + b_nq[t]]);
            const float* src = B + (size_t)(k0 + b_row[t]) * 128 + b_nq[t];
            cp_async16(dst, src, 16);
        }
        cp_commit();
    };

    float c[4][4][4];
#pragma unroll
    for (int mt = 0; mt < 4; mt++)
#pragma unroll
        for (int nt = 0; nt < 4; nt++)
#pragma unroll
            for (int f = 0; f < 4; f++) c[mt][nt][f] = 0.f;

    load_stage(0, 0);

    for (int it = 0; it < nIter; it++) {
        int cur = it & 1;
        if (it + 1 < nIter) {
            load_stage(it + 1, cur ^ 1);
            cp_wait<1>();
        } else {
            cp_wait<0>();
        }
        __syncthreads();

        uint32_t* as = As[cur];
        uint32_t* bs = Bs[cur];
#pragma unroll
        for (int ks = 0; ks < 4; ks++) {
            int kb = ks * 8;
            uint32_t a[4][4];
#pragma unroll
            for (int mt = 0; mt < 4; mt++) {
                int mb = warp_m * 64 + mt * 16;
                a[mt][0] = as[(mb + grp)     * AS_STRIDE + kb + tig];
                a[mt][1] = as[(mb + grp + 8) * AS_STRIDE + kb + tig];
                a[mt][2] = as[(mb + grp)     * AS_STRIDE + kb + tig + 4];
                a[mt][3] = as[(mb + grp + 8) * AS_STRIDE + kb + tig + 4];
            }
            uint32_t b[4][2];
#pragma unroll
            for (int nt = 0; nt < 4; nt++) {
                int nb = warp_n * 32 + nt * 8;
                b[nt][0] = bs[(kb + tig)     * BS_STRIDE + nb + grp];
                b[nt][1] = bs[(kb + tig + 4) * BS_STRIDE + nb + grp];
            }
#pragma unroll
            for (int mt = 0; mt < 4; mt++)
#pragma unroll
                for (int nt = 0; nt < 4; nt++)
                    mma_tf32(c[mt][nt], a[mt][0], a[mt][1], a[mt][2], a[mt][3],
                             b[nt][0], b[nt][1]);
        }
        __syncthreads();
    }

#pragma unroll
    for (int mt = 0; mt < 4; mt++) {
        int row0 = blockRow + warp_m * 64 + mt * 16 + grp;
        int row1 = row0 + 8;
#pragma unroll
        for (int nt = 0; nt < 4; nt++) {
            int col = warp_n * 32 + nt * 8 + 2 * tig;
            float v0 = c[mt][nt][0], v1 = c[mt][nt][1];
            float v2 = c[mt][nt][2], v3 = c[mt][nt][3];
            v0 = (v0 > 0.f) ? v0 : 0.2f * v0;
            v1 = (v1 > 0.f) ? v1 : 0.2f * v1;
            v2 = (v2 > 0.f) ? v2 : 0.2f * v2;
            v3 = (v3 > 0.f) ? v3 : 0.2f * v3;
            if (row0 < M) *(float2*)(L + (size_t)row0 * 128 + col) = make_float2(v0, v1);
            if (row1 < M) *(float2*)(L + (size_t)row1 * 128 + col) = make_float2(v2, v3);
        }
    }
}

// ---------------- helpers ----------------
__device__ __forceinline__ void store_h4(__half* base, size_t row, int lane, float4 v) {
    __half2 h0 = __floats2half2_rn(v.x, v.y);
    __half2 h1 = __floats2half2_rn(v.z, v.w);
    uint2 r;
    r.x = *reinterpret_cast<uint32_t*>(&h0);
    r.y = *reinterpret_cast<uint32_t*>(&h1);
    *((uint2*)(base + row * DIM) + lane) = r;
}
__device__ __forceinline__ float4 load_h4(const __half* base, size_t row, int lane) {
    uint2 raw = __ldg((const uint2*)(base + row * DIM) + lane);
    __half2 h0 = *reinterpret_cast<__half2*>(&raw.x);
    __half2 h1 = *reinterpret_cast<__half2*>(&raw.y);
    float2 f0 = __half22float2(h0), f1 = __half22float2(h1);
    return make_float4(f0.x, f0.y, f1.x, f1.y);
}

// ---------------- weighted combine + l2norm, both pairs in one launch ----------------
__global__ void combine_l2norm2_kernel(const float* __restrict__ La0, const float* __restrict__ Lb0,
                                       const float* __restrict__ La1, const float* __restrict__ Lb1,
                                       const float* __restrict__ mw,
                                       __half* __restrict__ out0, __half* __restrict__ out1,
                                       int nrows)
{
    int wid = (blockIdx.x * blockDim.x + threadIdx.x) >> 5;
    int lane = threadIdx.x & 31;
    if (wid >= nrows) return;
    const float* La = blockIdx.y ? La1 : La0;
    const float* Lb = blockIdx.y ? Lb1 : Lb0;
    __half* outh = blockIdx.y ? out1 : out0;
    float m0 = mw[0], m1 = mw[1];
    float mx = fmaxf(m0, m1);
    float e0 = __expf(m0 - mx), e1 = __expf(m1 - mx);
    float w0 = e0 / (e0 + e1), w1 = e1 / (e0 + e1);
    size_t off = (size_t)wid * DIM + lane * 4;
    float4 a = *(const float4*)(La + off);
    float4 b = *(const float4*)(Lb + off);
    float4 v;
    v.x = w0 * a.x + w1 * b.x;
    v.y = w0 * a.y + w1 * b.y;
    v.z = w0 * a.z + w1 * b.z;
    v.w = w0 * a.w + w1 * b.w;
    float s = v.x * v.x + v.y * v.y + v.z * v.z + v.w * v.w;
#pragma unroll
    for (int o = 16; o > 0; o >>= 1) s += __shfl_xor_sync(0xffffffffu, s, o);
    float inv = 1.f / fmaxf(sqrtf(s), 1e-12f);
    v.x *= inv; v.y *= inv; v.z *= inv; v.w *= inv;
    store_h4(outh, wid, lane, v);
}

// ---------------- fp16-gather CSR SpMM (warp per row) ----------------
__device__ __forceinline__ float4 gfetch_h(int col, int lane,
                                           const __half* __restrict__ xU,
                                           const __half* __restrict__ xI) {
    const __half* x = (col < USERS) ? (xU + (size_t)col * DIM)
                                    : (xI + (size_t)(col - USERS) * DIM);
    uint2 raw = __ldg((const uint2*)x + lane);
    __half2 h0 = *reinterpret_cast<__half2*>(&raw.x);
    __half2 h1 = *reinterpret_cast<__half2*>(&raw.y);
    float2 f0 = __half22float2(h0), f1 = __half22float2(h1);
    return make_float4(f0.x, f0.y, f1.x, f1.y);
}
__device__ __forceinline__ void facc(float4& a, float w, float4 x) {
    a.x += w * x.x; a.y += w * x.y; a.z += w * x.z; a.w += w * x.w;
}

// generic single-table spmm body, 8x unrolled
__device__ __forceinline__ float4 spmm_row(const float2* __restrict__ cv, int s, int e, int lane,
                                           const __half* __restrict__ xU,
                                           const __half* __restrict__ xI)
{
    float4 acc = make_float4(0.f, 0.f, 0.f, 0.f);
    int i = s;
    for (; i + 8 <= e; i += 8) {
        float2 cc[8];
        float4 xv[8];
#pragma unroll
        for (int u = 0; u < 8; u++) cc[u] = cv[i + u];
#pragma unroll
        for (int u = 0; u < 8; u++) xv[u] = gfetch_h(__float_as_int(cc[u].x), lane, xU, xI);
#pragma unroll
        for (int u = 0; u < 8; u++) facc(acc, cc[u].y, xv[u]);
    }
    for (; i < e; i++) {
        float2 c0 = cv[i];
        facc(acc, c0.y, gfetch_h(__float_as_int(c0.x), lane, xU, xI));
    }
    return acc;
}

// single-table spmm: fp32 out + optional fp16 out
__global__ void spmm_h_kernel(const int* __restrict__ rowptr, const float2* __restrict__ cv,
                              const __half* __restrict__ xU, const __half* __restrict__ xI,
                              float* __restrict__ out, __half* __restrict__ outh)
{
    int row = blockIdx.x * 8 + (threadIdx.x >> 5);
    int lane = threadIdx.x & 31;
    if (row >= NTOT) return;
    float4 acc = spmm_row(cv, rowptr[row], rowptr[row + 1], lane, xU, xI);
    *((float4*)(out + (size_t)row * DIM) + lane) = acc;
    if (outh) store_h4(outh, row, lane, acc);
}

// two independent single-table spmms (same gather tables) in one launch
__global__ void spmm_h_pair_kernel(const int* __restrict__ rp0, const int* __restrict__ rp1,
                                   const float2* __restrict__ cv,
                                   const __half* __restrict__ xU, const __half* __restrict__ xI,
                                   float* __restrict__ out0, float* __restrict__ out1)
{
    int row = blockIdx.x * 8 + (threadIdx.x >> 5);
    int lane = threadIdx.x & 31;
    if (row >= NTOT) return;
    const int* rowptr = blockIdx.y ? rp1 : rp0;
    float* out = blockIdx.y ? out1 : out0;
    float4 acc = spmm_row(cv, rowptr[row], rowptr[row + 1], lane, xU, xI);
    *((float4*)(out + (size_t)row * DIM) + lane) = acc;
}

// Dual SpMM, shared USER table, 4x unrolled; fp16-ONLY outputs.
__global__ void spmm_h_dualU_kernel(const int* __restrict__ rowptr, const float2* __restrict__ cv,
                                    const __half* __restrict__ xU,
                                    const __half* __restrict__ xIa, const __half* __restrict__ xIb,
                                    __half* __restrict__ outAh, __half* __restrict__ outBh)
{
    int row = blockIdx.x * 8 + (threadIdx.x >> 5);
    int lane = threadIdx.x & 31;
    if (row >= NTOT) return;
    int s = rowptr[row], e = rowptr[row + 1];
    float4 accA = make_float4(0.f, 0.f, 0.f, 0.f);
    float4 accB = make_float4(0.f, 0.f, 0.f, 0.f);
    int i = s;
    for (; i + 4 <= e; i += 4) {
        float2 cc[4];
        float4 xa[4], xb[4];
#pragma unroll
        for (int u = 0; u < 4; u++) cc[u] = cv[i + u];
#pragma unroll
        for (int u = 0; u < 4; u++) {
            int col = __float_as_int(cc[u].x);
            if (col < USERS) {
                xa[u] = gfetch_h(col, lane, xU, xU);
                xb[u] = xa[u];
            } else {
                xa[u] = gfetch_h(col, lane, xU, xIa);
                xb[u] = gfetch_h(col, lane, xU, xIb);
            }
        }
#pragma unroll
        for (int u = 0; u < 4; u++) {
            facc(accA, cc[u].y, xa[u]);
            facc(accB, cc[u].y, xb[u]);
        }
    }
    for (; i < e; i++) {
        float2 c = cv[i];
        int col = __float_as_int(c.x);
        float4 xa, xb;
        if (col < USERS) { xa = gfetch_h(col, lane, xU, xU); xb = xa; }
        else { xa = gfetch_h(col, lane, xU, xIa); xb = gfetch_h(col, lane, xU, xIb); }
        facc(accA, c.y, xa); facc(accB, c.y, xb);
    }
    store_h4(outAh, row, lane, accA);
    store_h4(outBh, row, lane, accB);
}

// Dual SpMM (shared ITEM table) FUSED with modal combine:
// accA = adj@[Id_u; iEmb], accB = adj@[Ft_u; iEmb];
// modal = 0.5*(Id + accA + 0.2*IdAdj) + 0.5*(Ft + accB + 0.2*FtAdj)  -> fp32 + fp16
__global__ void spmm_dualI_combine_kernel(const int* __restrict__ rowptr, const float2* __restrict__ cv,
                                          const __half* __restrict__ hId, const __half* __restrict__ hFt,
                                          const __half* __restrict__ xI,
                                          const float* __restrict__ idAdj, const float* __restrict__ ftAdj,
                                          float* __restrict__ modal, __half* __restrict__ modalh)
{
    int row = blockIdx.x * 8 + (threadIdx.x >> 5);
    int lane = threadIdx.x & 31;
    if (row >= NTOT) return;
    int s = rowptr[row], e = rowptr[row + 1];
    float4 accA = make_float4(0.f, 0.f, 0.f, 0.f);
    float4 accB = make_float4(0.f, 0.f, 0.f, 0.f);
    int i = s;
    for (; i + 4 <= e; i += 4) {
        float2 cc[4];
        float4 xa[4], xb[4];
#pragma unroll
        for (int u = 0; u < 4; u++) cc[u] = cv[i + u];
#pragma unroll
        for (int u = 0; u < 4; u++) {
            int col = __float_as_int(cc[u].x);
            if (col < USERS) {
                xa[u] = gfetch_h(col, lane, hId, hId);
                xb[u] = gfetch_h(col, lane, hFt, hFt);
            } else {
                xa[u] = gfetch_h(col, lane, hId, xI);
                xb[u] = xa[u];
            }
        }
#pragma unroll
        for (int u = 0; u < 4; u++) {
            facc(accA, cc[u].y, xa[u]);
            facc(accB, cc[u].y, xb[u]);
        }
    }
    for (; i < e; i++) {
        float2 c = cv[i];
        int col = __float_as_int(c.x);
        float4 xa, xb;
        if (col < USERS) { xa = gfetch_h(col, lane, hId, hId); xb = gfetch_h(col, lane, hFt, hFt); }
        else { xa = gfetch_h(col, lane, hId, xI); xb = xa; }
        facc(accA, c.y, xa); facc(accB, c.y, xb);
    }
    // fused combine epilogue
    float4 idv = load_h4(hId, row, lane);
    float4 ftv = load_h4(hFt, row, lane);
    float4 ia = *((const float4*)(idAdj + (size_t)row * DIM) + lane);
    float4 fa = *((const float4*)(ftAdj + (size_t)row * DIM) + lane);
    float4 m;
    m.x = 0.5f * (idv.x + accA.x + 0.2f * ia.x) + 0.5f * (ftv.x + accB.x + 0.2f * fa.x);
    m.y = 0.5f * (idv.y + accA.y + 0.2f * ia.y) + 0.5f * (ftv.y + accB.y + 0.2f * fa.y);
    m.z = 0.5f * (idv.z + accA.z + 0.2f * ia.z) + 0.5f * (ftv.z + accB.z + 0.2f * fa.z);
    m.w = 0.5f * (idv.w + accA.w + 0.2f * ia.w) + 0.5f * (ftv.w + accB.w + 0.2f * fa.w);
    *((float4*)(modal + (size_t)row * DIM) + lane) = m;
    store_h4(modalh, row, lane, m);
}

// GNN layer-2 SpMM FUSED with final: out = modal + A + acc + (0.5/||modal||)*modal
__global__ void spmm_final_kernel(const int* __restrict__ rowptr, const float2* __restrict__ cv,
                                  const __half* __restrict__ xU, const __half* __restrict__ xI,
                                  const float* __restrict__ modal, const float* __restrict__ A,
                                  float* __restrict__ out)
{
    int row = blockIdx.x * 8 + (threadIdx.x >> 5);
    int lane = threadIdx.x & 31;
    if (row >= NTOT) return;
    float4 acc = spmm_row(cv, rowptr[row], rowptr[row + 1], lane, xU, xI);
    size_t off = (size_t)row * DIM + lane * 4;
    float4 m = *(const float4*)(modal + off);
    float4 a = *(const float4*)(A + off);
    float s = m.x * m.x + m.y * m.y + m.z * m.z + m.w * m.w;
#pragma unroll
    for (int o = 16; o > 0; o >>= 1) s += __shfl_xor_sync(0xffffffffu, s, o);
    float inv = 0.5f / fmaxf(sqrtf(s), 1e-12f);   // RIS_LAMBDA / norm
    float4 r;
    r.x = m.x + a.x + acc.x + inv * m.x;
    r.y = m.y + a.y + acc.y + inv * m.y;
    r.z = m.z + a.z + acc.z + inv * m.z;
    r.w = m.w + a.w + acc.w + inv * m.w;
    *(float4*)(out + off) = r;
}

// ---------------- host ----------------
extern "C" void kernel_launch(void* const* d_in, const int* in_sizes, int n_in,
                              void* d_out, int out_size)
{
    const int*   adj_rows = (const int*)d_in[0];
    const int*   adj_cols = (const int*)d_in[1];
    const float* adj_vals = (const float*)d_in[2];
    const int*   id_rows  = (const int*)d_in[3];
    const int*   id_cols  = (const int*)d_in[4];
    const float* id_vals  = (const float*)d_in[5];
    const int*   ft_rows  = (const int*)d_in[6];
    const int*   ft_cols  = (const int*)d_in[7];
    const float* ft_vals  = (const float*)d_in[8];
    const float* uEmb     = (const float*)d_in[9];
    const float* iEmb     = (const float*)d_in[10];
    const float* img_emb  = (const float*)d_in[11];
    const float* img_id   = (const float*)d_in[12];
    const float* txt_emb  = (const float*)d_in[13];
    const float* txt_id   = (const float*)d_in[14];
    const float* img_tr   = (const float*)d_in[15];
    const float* img_id_tr= (const float*)d_in[16];
    const float* txt_tr   = (const float*)d_in[17];
    const float* txt_id_tr= (const float*)d_in[18];
    const float* mw       = (const float*)d_in[19];
    float* out = (float*)d_out;

    int E_adj = in_sizes[0];
    int E_id  = in_sizes[3];
    int E_ft  = in_sizes[6];
    int E_tot = E_adj + E_id + E_ft;

    float *pIdAdj, *pFtAdj, *pModal, *pA, *pB;
    __half *hU, *hI, *hAllID, *hAllFt, *hId, *hFt, *hModal, *hA;
    float2 *cvAll;
    int *pRp, *pCounts, *pOffs, *pBsums;
    cudaGetSymbolAddress((void**)&pIdAdj,  g_IdAdj);
    cudaGetSymbolAddress((void**)&pFtAdj,  g_FtAdj);
    cudaGetSymbolAddress((void**)&pModal,  g_modal);
    cudaGetSymbolAddress((void**)&pA,      g_tmpA);
    cudaGetSymbolAddress((void**)&pB,      g_tmpB);
    cudaGetSymbolAddress((void**)&hU,      g_h_u);
    cudaGetSymbolAddress((void**)&hI,      g_h_i);
    cudaGetSymbolAddress((void**)&hAllID,  g_h_allID);
    cudaGetSymbolAddress((void**)&hAllFt,  g_h_allFt);
    cudaGetSymbolAddress((void**)&hId,     g_h_Id);
    cudaGetSymbolAddress((void**)&hFt,     g_h_Ft);
    cudaGetSymbolAddress((void**)&hModal,  g_h_modal);
    cudaGetSymbolAddress((void**)&hA,      g_h_A);
    cudaGetSymbolAddress((void**)&cvAll,   g_cv_all);
    cudaGetSymbolAddress((void**)&pRp,     g_rp);
    cudaGetSymbolAddress((void**)&pCounts, g_counts);
    cudaGetSymbolAddress((void**)&pOffs,   g_offs);
    cudaGetSymbolAddress((void**)&pBsums,  g_bsums);

    static cudaStream_t s1 = nullptr;
    static cudaEvent_t evFork = nullptr, evGemmDone = nullptr;
    static bool inited = false;
    if (!inited) {
        cudaStreamCreateWithFlags(&s1, cudaStreamNonBlocking);
        cudaEventCreateWithFlags(&evFork, cudaEventDisableTiming);
        cudaEventCreateWithFlags(&evGemmDone, cudaEventDisableTiming);
        cudaFuncSetAttribute(gemm4_kernel, cudaFuncAttributeMaxDynamicSharedMemorySize,
                             GEMM_SMEM_BYTES);
        inited = true;
    }

    // GEMM lrelu buffers live in g_tmpA/g_tmpB (free until GNN layer 1 / never reused for pB)
    float* L_imgid = pA;
    float* L_txtid = pA + (size_t)ITEMS * DIM;
    float* L_img   = pB;
    float* L_txt   = pB + (size_t)ITEMS * DIM;

    // ---- fork: GEMM arm on s1, sparse arm on stream 0 ----
    cudaEventRecord(evFork, 0);
    cudaStreamWaitEvent(s1, evFork, 0);

    {
        dim3 ggrid((ITEMS + 127) / 128, 4);
        gemm4_kernel<<<ggrid, 256, GEMM_SMEM_BYTES, s1>>>(
            img_id, txt_id, img_emb, txt_emb,
            img_id_tr, txt_id_tr, img_tr, txt_tr,
            L_imgid, L_txtid, L_img, L_txt);
        dim3 cgrid((ITEMS * 32 + 255) / 256, 2);
        combine_l2norm2_kernel<<<cgrid, 256, 0, s1>>>(L_imgid, L_txtid, L_img, L_txt,
                                                      mw, hAllID, hAllFt, ITEMS);
        cudaEventRecord(evGemmDone, s1);
    }

    // stream 0: batched CSR build
    {
        int n = 3 * NSEG;
        int nb = (n + SCAN_BLOCK - 1) / SCAN_BLOCK;
        zero_int_kernel<<<(n + 255) / 256, 256>>>(pCounts, n);
        hist3_kernel<<<(E_tot + 255) / 256, 256>>>(adj_rows, id_rows, ft_rows,
                                                   E_adj, E_id, E_ft, pCounts);
        scan1_kernel<<<nb, SCAN_BLOCK>>>(pCounts, pRp, pBsums, n);
        scan2_kernel<<<1, NB_MAX>>>(pBsums, nb);
        scan3_kernel<<<nb, SCAN_BLOCK>>>(pRp, pBsums, pOffs, n);
        scatter3_kernel<<<(E_tot + 255) / 256, 256>>>(adj_rows, adj_cols, adj_vals,
                                                      id_rows, id_cols, id_vals,
                                                      ft_rows, ft_cols, ft_vals,
                                                      E_adj, E_id, E_ft, pOffs, cvAll);
    }
    const int* rpAdj = pRp;
    const int* rpId  = pRp + NSEG;
    const int* rpFt  = pRp + 2 * NSEG;

    // stream 0: fp16 input tables + the two input-only spmms (overlap GEMM arm)
    {
        int n4u = USERS * DIM / 4;
        f2h2_kernel<<<(2 * n4u + 255) / 256, 256>>>((const float4*)uEmb, (const float4*)iEmb,
                                                    (uint2*)hU, (uint2*)hI, n4u);
    }
    int spmm_blocks = (NTOT + 7) / 8;
    {
        dim3 pgrid(spmm_blocks, 2);
        spmm_h_pair_kernel<<<pgrid, 256>>>(rpId, rpFt, cvAll, hU, hI, pIdAdj, pFtAdj);
    }

    // ---- join ----
    cudaStreamWaitEvent(0, evGemmDone, 0);

    // first-hop dual SpMM -> fp16 Id/Ft only
    spmm_h_dualU_kernel<<<spmm_blocks, 256>>>(rpAdj, cvAll, hU, hAllID, hAllFt, hId, hFt);
    // second-hop dual SpMM fused with modal combine
    spmm_dualI_combine_kernel<<<spmm_blocks, 256>>>(rpAdj, cvAll, hId, hFt, hI,
                                                    pIdAdj, pFtAdj, pModal, hModal);
    // GNN layer 1 (fp32 + fp16 out); overwrites g_tmpA (GEMM buffers consumed)
    spmm_h_kernel<<<spmm_blocks, 256>>>(rpAdj, cvAll, hModal, hModal + (size_t)USERS * DIM, pA, hA);
    // GNN layer 2 fused with final
    spmm_final_kernel<<<spmm_blocks, 256>>>(rpAdj, cvAll, hA, hA + (size_t)USERS * DIM,
                                            pModal, pA, out);

    (void)n_in; (void)out_size;
}